// round 3
// baseline (speedup 1.0000x reference)
#include <cuda_runtime.h>
#include <math.h>
#include <stdint.h>

#define Bsz 2
#define Lseq 2048
#define Dm 1024
#define Hh 16
#define HDd 64
#define BL (Bsz*Lseq)   // 4096

// ---------------- scratch (static device globals; no allocation) ----------------
__device__ float g_qkv[BL*3*Dm];
__device__ float g_attn[BL*Dm];
__device__ float g_flash[BL*Dm];
__device__ float g_dqr[BL*Dm];
__device__ float g_dkr[BL*Dm];
__device__ float g_dq[BL*Dm];
__device__ float g_dk[BL*Dm];
__device__ float g_dv[BL*Dm];
__device__ float g_beta[BL*Hh];
__device__ float g_ys[BL*Dm];
__device__ float g_delta[BL*Dm];
__device__ float g_gate[BL*Dm];

// ---------------- tf32 helpers ----------------
__device__ __forceinline__ float f2tf32(float x) {
    float r;
    asm("cvt.rna.tf32.f32 %0, %1;" : "=f"(r) : "f"(x));
    return r;
}

__device__ __forceinline__ void mma_tf32(float& c0, float& c1, float& c2, float& c3,
                                         unsigned a0, unsigned a1, unsigned a2, unsigned a3,
                                         unsigned b0, unsigned b1) {
    asm volatile("mma.sync.aligned.m16n8k8.row.col.f32.tf32.tf32.f32 "
                 "{%0,%1,%2,%3}, {%4,%5,%6,%7}, {%8,%9}, {%0,%1,%2,%3};"
                 : "+f"(c0), "+f"(c1), "+f"(c2), "+f"(c3)
                 : "r"(a0), "r"(a1), "r"(a2), "r"(a3), "r"(b0), "r"(b1));
}

// ---------------- tf32 tensor-core GEMM (optionally 3xTF32 precise) ----------------
// C[M,N] = A[M,K] @ B[K,N], row-major fp32 in/out.
// BM=128, BN=128, BK=32, 256 threads (8 warps, 2x4), warp tile 64x32.
#define AS_STRIDE 36
#define BS_STRIDE 132
#define ABUF (128*AS_STRIDE)
#define BBUF (32*BS_STRIDE)
#define GEMM_SMEM_FAST ((2*ABUF + 2*BBUF) * 4)
#define GEMM_SMEM_P3   ((4*ABUF + 4*BBUF) * 4)

template<bool P3>
__device__ __forceinline__ void stage_tile(float* Ah, float* Al, float* Bh, float* Bl,
                                           const float4* ra, const float4* rb, int tid) {
#pragma unroll
    for (int i = 0; i < 4; i++) {
        int e = tid + i * 256;
        int ar = e >> 3, ac = (e & 7) * 4;
        float* ap = &Ah[ar * AS_STRIDE + ac];
        float4 v = ra[i];
        float h0 = f2tf32(v.x), h1 = f2tf32(v.y), h2 = f2tf32(v.z), h3 = f2tf32(v.w);
        ap[0] = h0; ap[1] = h1; ap[2] = h2; ap[3] = h3;
        if (P3) {
            float* al = &Al[ar * AS_STRIDE + ac];
            al[0] = f2tf32(v.x - h0); al[1] = f2tf32(v.y - h1);
            al[2] = f2tf32(v.z - h2); al[3] = f2tf32(v.w - h3);
        }
        int br = e >> 5, bc = (e & 31) * 4;
        float4 w = rb[i];
        float g0 = f2tf32(w.x), g1 = f2tf32(w.y), g2 = f2tf32(w.z), g3 = f2tf32(w.w);
        *(float4*)&Bh[br * BS_STRIDE + bc] = make_float4(g0, g1, g2, g3);
        if (P3) {
            *(float4*)&Bl[br * BS_STRIDE + bc] =
                make_float4(f2tf32(w.x - g0), f2tf32(w.y - g1),
                            f2tf32(w.z - g2), f2tf32(w.w - g3));
        }
    }
}

template<bool P3>
__global__ void gemm_tf32_t(const float* __restrict__ A, const float* __restrict__ B,
                            float* __restrict__ C, int M, int N, int K) {
    extern __shared__ float sm[];
    float* Ah = sm;                         // [2][128][36]
    float* Bh = sm + 2 * ABUF;              // [2][32][132]
    float* Al = P3 ? sm + 2 * ABUF + 2 * BBUF : sm;
    float* Bl = P3 ? Al + 2 * ABUF : sm;

    int tid = threadIdx.x;
    int warp = tid >> 5, lane = tid & 31;
    int gid = lane >> 2, tig = lane & 3;
    int warp_m = (warp >> 2) * 64;
    int warp_n = (warp & 3) * 32;
    int m0 = blockIdx.y * 128, n0 = blockIdx.x * 128;

    float acc[4][4][4];
#pragma unroll
    for (int i = 0; i < 4; i++)
#pragma unroll
        for (int j = 0; j < 4; j++)
#pragma unroll
            for (int u = 0; u < 4; u++) acc[i][j][u] = 0.f;

    float4 ra[4], rb[4];
    int kt_total = K >> 5;

    // prologue: load tile 0
#pragma unroll
    for (int i = 0; i < 4; i++) {
        int e = tid + i * 256;
        int ar = e >> 3, ac = (e & 7) * 4;
        ra[i] = *(const float4*)&A[(size_t)(m0 + ar) * K + ac];
        int br = e >> 5, bc = (e & 31) * 4;
        rb[i] = *(const float4*)&B[(size_t)br * N + n0 + bc];
    }
    stage_tile<P3>(Ah, Al, Bh, Bl, ra, rb, tid);
    __syncthreads();

    for (int t = 0; t < kt_total; t++) {
        int cur = t & 1;
        float* Ahc = Ah + cur * ABUF;
        float* Bhc = Bh + cur * BBUF;
        float* Alc = Al + cur * ABUF;
        float* Blc = Bl + cur * BBUF;

        if (t + 1 < kt_total) {
            int kk = (t + 1) << 5;
#pragma unroll
            for (int i = 0; i < 4; i++) {
                int e = tid + i * 256;
                int ar = e >> 3, ac = (e & 7) * 4;
                ra[i] = *(const float4*)&A[(size_t)(m0 + ar) * K + kk + ac];
                int br = e >> 5, bc = (e & 31) * 4;
                rb[i] = *(const float4*)&B[(size_t)(kk + br) * N + n0 + bc];
            }
        }

#pragma unroll
        for (int ks = 0; ks < 4; ks++) {
            int k0 = ks * 8;
            unsigned afh[4][4], bfh[4][2];
            unsigned afl[4][4], bfl[4][2];
#pragma unroll
            for (int mt = 0; mt < 4; mt++) {
                int r = warp_m + mt * 16 + gid;
                const float* ap = &Ahc[r * AS_STRIDE + k0 + tig];
                afh[mt][0] = __float_as_uint(ap[0]);
                afh[mt][1] = __float_as_uint(ap[AS_STRIDE * 8]);
                afh[mt][2] = __float_as_uint(ap[4]);
                afh[mt][3] = __float_as_uint(ap[AS_STRIDE * 8 + 4]);
                if (P3) {
                    const float* al = &Alc[r * AS_STRIDE + k0 + tig];
                    afl[mt][0] = __float_as_uint(al[0]);
                    afl[mt][1] = __float_as_uint(al[AS_STRIDE * 8]);
                    afl[mt][2] = __float_as_uint(al[4]);
                    afl[mt][3] = __float_as_uint(al[AS_STRIDE * 8 + 4]);
                }
            }
#pragma unroll
            for (int nt = 0; nt < 4; nt++) {
                int c = warp_n + nt * 8 + gid;
                const float* bp = &Bhc[(k0 + tig) * BS_STRIDE + c];
                bfh[nt][0] = __float_as_uint(bp[0]);
                bfh[nt][1] = __float_as_uint(bp[BS_STRIDE * 4]);
                if (P3) {
                    const float* bl = &Blc[(k0 + tig) * BS_STRIDE + c];
                    bfl[nt][0] = __float_as_uint(bl[0]);
                    bfl[nt][1] = __float_as_uint(bl[BS_STRIDE * 4]);
                }
            }
#pragma unroll
            for (int mt = 0; mt < 4; mt++)
#pragma unroll
                for (int nt = 0; nt < 4; nt++) {
                    if (P3) {
                        mma_tf32(acc[mt][nt][0], acc[mt][nt][1], acc[mt][nt][2], acc[mt][nt][3],
                                 afh[mt][0], afh[mt][1], afh[mt][2], afh[mt][3],
                                 bfl[nt][0], bfl[nt][1]);
                        mma_tf32(acc[mt][nt][0], acc[mt][nt][1], acc[mt][nt][2], acc[mt][nt][3],
                                 afl[mt][0], afl[mt][1], afl[mt][2], afl[mt][3],
                                 bfh[nt][0], bfh[nt][1]);
                    }
                    mma_tf32(acc[mt][nt][0], acc[mt][nt][1], acc[mt][nt][2], acc[mt][nt][3],
                             afh[mt][0], afh[mt][1], afh[mt][2], afh[mt][3],
                             bfh[nt][0], bfh[nt][1]);
                }
        }

        if (t + 1 < kt_total) {
            int nxt = (t + 1) & 1;
            stage_tile<P3>(Ah + nxt * ABUF, Al + nxt * ABUF,
                           Bh + nxt * BBUF, Bl + nxt * BBUF, ra, rb, tid);
        }
        __syncthreads();
    }

    // epilogue
#pragma unroll
    for (int mt = 0; mt < 4; mt++) {
#pragma unroll
        for (int nt = 0; nt < 4; nt++) {
            int row = m0 + warp_m + mt * 16 + gid;
            int col = n0 + warp_n + nt * 8 + 2 * tig;
            *(float2*)&C[(size_t)row * N + col] =
                make_float2(acc[mt][nt][0], acc[mt][nt][1]);
            *(float2*)&C[(size_t)(row + 8) * N + col] =
                make_float2(acc[mt][nt][2], acc[mt][nt][3]);
        }
    }
}

// ---------------- small SGEMM (for Wbeta, N=16) ----------------
__global__ void gemm128(const float* __restrict__ A, const float* __restrict__ Bm,
                        float* __restrict__ C, int M, int N, int K) {
    __shared__ float As[16][128];
    __shared__ float Bs[16][64];
    int tid = threadIdx.x;
    int tx = tid & 15, ty = tid >> 4;
    int m0 = blockIdx.y * 128, n0 = blockIdx.x * 64;

    int arow = tid >> 2;
    int ak4  = (tid & 3) * 4;
    int brow = tid >> 4;
    int bc4  = (tid & 15) * 4;

    float acc[8][4];
#pragma unroll
    for (int i = 0; i < 8; i++)
#pragma unroll
        for (int j = 0; j < 4; j++) acc[i][j] = 0.f;

    for (int kk = 0; kk < K; kk += 16) {
#pragma unroll
        for (int half = 0; half < 2; half++) {
            int r = arow + half * 64;
            float4 a4 = *(const float4*)&A[(size_t)(m0 + r) * K + kk + ak4];
            As[ak4 + 0][r] = a4.x; As[ak4 + 1][r] = a4.y;
            As[ak4 + 2][r] = a4.z; As[ak4 + 3][r] = a4.w;
        }
        if (n0 + bc4 < N) {
            *(float4*)&Bs[brow][bc4] = *(const float4*)&Bm[(size_t)(kk + brow) * N + n0 + bc4];
        } else {
            *(float4*)&Bs[brow][bc4] = make_float4(0.f, 0.f, 0.f, 0.f);
        }
        __syncthreads();
#pragma unroll
        for (int k2 = 0; k2 < 16; k2++) {
            float4 b4 = *(float4*)&Bs[k2][tx * 4];
            float4 aa = *(float4*)&As[k2][ty * 8];
            float4 ab = *(float4*)&As[k2][ty * 8 + 4];
            float av[8] = {aa.x, aa.y, aa.z, aa.w, ab.x, ab.y, ab.z, ab.w};
            float bv[4] = {b4.x, b4.y, b4.z, b4.w};
#pragma unroll
            for (int i = 0; i < 8; i++)
#pragma unroll
                for (int j = 0; j < 4; j++) acc[i][j] += av[i] * bv[j];
        }
        __syncthreads();
    }
    if (n0 + tx * 4 < N) {
#pragma unroll
        for (int i = 0; i < 8; i++) {
            int row = m0 + ty * 8 + i;
            float4 o = make_float4(acc[i][0], acc[i][1], acc[i][2], acc[i][3]);
            *(float4*)&C[(size_t)row * N + n0 + tx * 4] = o;
        }
    }
}

// ---------------- conv (causal depthwise, KW=4) + k-normalization ----------------
__global__ void conv_kernel(const float* __restrict__ dqr, const float* __restrict__ dkr,
                            const float* __restrict__ cqw, const float* __restrict__ cqb,
                            const float* __restrict__ ckw, const float* __restrict__ ckb,
                            float* __restrict__ dq, float* __restrict__ dk) {
    int bt = blockIdx.x;
    int t  = bt & (Lseq - 1);
    int tid = threadIdx.x;
    int c0 = tid * 4;

    float xq[4][4], xk[4][4];
#pragma unroll
    for (int j = 0; j < 4; j++) {
        int tt = t - 3 + j;
        if (tt >= 0) {
            float4 a = *(const float4*)&dqr[(size_t)(bt - 3 + j) * Dm + c0];
            xq[j][0] = a.x; xq[j][1] = a.y; xq[j][2] = a.z; xq[j][3] = a.w;
            float4 b = *(const float4*)&dkr[(size_t)(bt - 3 + j) * Dm + c0];
            xk[j][0] = b.x; xk[j][1] = b.y; xk[j][2] = b.z; xk[j][3] = b.w;
        } else {
#pragma unroll
            for (int u = 0; u < 4; u++) { xq[j][u] = 0.f; xk[j][u] = 0.f; }
        }
    }
    float4 qb4 = *(const float4*)&cqb[c0];
    float4 kb4 = *(const float4*)&ckb[c0];
    float qbv[4] = {qb4.x, qb4.y, qb4.z, qb4.w};
    float kbv[4] = {kb4.x, kb4.y, kb4.z, kb4.w};

    float oq[4], ok[4];
#pragma unroll
    for (int u = 0; u < 4; u++) {
        float4 wq = *(const float4*)&cqw[(c0 + u) * 4];
        float4 wk = *(const float4*)&ckw[(c0 + u) * 4];
        oq[u] = qbv[u] + wq.x * xq[0][u] + wq.y * xq[1][u] + wq.z * xq[2][u] + wq.w * xq[3][u];
        ok[u] = kbv[u] + wk.x * xk[0][u] + wk.y * xk[1][u] + wk.z * xk[2][u] + wk.w * xk[3][u];
    }
    *(float4*)&dq[(size_t)bt * Dm + c0] = make_float4(oq[0], oq[1], oq[2], oq[3]);

    float ss = ok[0] * ok[0] + ok[1] * ok[1] + ok[2] * ok[2] + ok[3] * ok[3];
    ss += __shfl_xor_sync(0xffffffffu, ss, 1, 16);
    ss += __shfl_xor_sync(0xffffffffu, ss, 2, 16);
    ss += __shfl_xor_sync(0xffffffffu, ss, 4, 16);
    ss += __shfl_xor_sync(0xffffffffu, ss, 8, 16);
    float rn = 1.f / fmaxf(sqrtf(ss), 1e-12f);
    *(float4*)&dk[(size_t)bt * Dm + c0] =
        make_float4(ok[0] * rn, ok[1] * rn, ok[2] * rn, ok[3] * rn);
}

// ---------------- causal flash attention (fp32, streaming) ----------------
__global__ void attn_kernel(const float* __restrict__ qkv, float* __restrict__ out) {
    extern __shared__ float sm[];
    float (*Qs)[64] = (float(*)[64])(sm);
    float (*Ks)[64] = (float(*)[64])(sm + 4096);
    float (*Vs)[64] = (float(*)[64])(sm + 8192);
    float (*Ps)[64] = (float(*)[64])(sm + 12288);

    int qt = blockIdx.x, bh = blockIdx.y;
    int b = bh >> 4, h = bh & 15;
    int tid = threadIdx.x;
    int tx = tid & 15, ty = tid >> 4;
    int q0 = qt * 64;
    size_t qkvbase = (size_t)(b * Lseq) * 3072 + h * 64;

    int lr = tid >> 2;
    int ldb = (tid & 3) * 16;

#pragma unroll
    for (int i = 0; i < 16; i += 4) {
        float4 a = *(const float4*)&qkv[qkvbase + (size_t)(q0 + lr) * 3072 + ldb + i];
        Qs[ldb + i + 0][lr] = a.x; Qs[ldb + i + 1][lr] = a.y;
        Qs[ldb + i + 2][lr] = a.z; Qs[ldb + i + 3][lr] = a.w;
    }

    float acc[4][4];
    float m_i[4], l_i[4];
#pragma unroll
    for (int i = 0; i < 4; i++) {
        m_i[i] = -1e30f; l_i[i] = 0.f;
#pragma unroll
        for (int j = 0; j < 4; j++) acc[i][j] = 0.f;
    }
    __syncthreads();

    for (int kt = 0; kt <= qt; kt++) {
        int k0 = kt * 64;
#pragma unroll
        for (int i = 0; i < 16; i += 4) {
            float4 a = *(const float4*)&qkv[qkvbase + 1024 + (size_t)(k0 + lr) * 3072 + ldb + i];
            Ks[ldb + i + 0][lr] = a.x; Ks[ldb + i + 1][lr] = a.y;
            Ks[ldb + i + 2][lr] = a.z; Ks[ldb + i + 3][lr] = a.w;
            float4 v = *(const float4*)&qkv[qkvbase + 2048 + (size_t)(k0 + lr) * 3072 + ldb + i];
            *(float4*)&Vs[lr][ldb + i] = v;
        }
        __syncthreads();

        float s[4][4];
#pragma unroll
        for (int i = 0; i < 4; i++)
#pragma unroll
            for (int j = 0; j < 4; j++) s[i][j] = 0.f;
#pragma unroll
        for (int d = 0; d < 64; d++) {
            float4 a = *(float4*)&Qs[d][ty * 4];
            float4 bq = *(float4*)&Ks[d][tx * 4];
            float av[4] = {a.x, a.y, a.z, a.w};
            float bv[4] = {bq.x, bq.y, bq.z, bq.w};
#pragma unroll
            for (int i = 0; i < 4; i++)
#pragma unroll
                for (int j = 0; j < 4; j++) s[i][j] += av[i] * bv[j];
        }
        if (kt == qt) {
#pragma unroll
            for (int i = 0; i < 4; i++)
#pragma unroll
                for (int j = 0; j < 4; j++) {
                    if (tx * 4 + j > ty * 4 + i) s[i][j] = -1e30f;
                    else s[i][j] *= 0.125f;
                }
        } else {
#pragma unroll
            for (int i = 0; i < 4; i++)
#pragma unroll
                for (int j = 0; j < 4; j++) s[i][j] *= 0.125f;
        }
#pragma unroll
        for (int i = 0; i < 4; i++) {
            float mm = fmaxf(fmaxf(s[i][0], s[i][1]), fmaxf(s[i][2], s[i][3]));
            mm = fmaxf(mm, __shfl_xor_sync(0xffffffffu, mm, 1, 16));
            mm = fmaxf(mm, __shfl_xor_sync(0xffffffffu, mm, 2, 16));
            mm = fmaxf(mm, __shfl_xor_sync(0xffffffffu, mm, 4, 16));
            mm = fmaxf(mm, __shfl_xor_sync(0xffffffffu, mm, 8, 16));
            float mt = fmaxf(m_i[i], mm);
            float alpha = __expf(m_i[i] - mt);
            m_i[i] = mt;
            float rs = 0.f;
#pragma unroll
            for (int j = 0; j < 4; j++) { s[i][j] = __expf(s[i][j] - mt); rs += s[i][j]; }
            rs += __shfl_xor_sync(0xffffffffu, rs, 1, 16);
            rs += __shfl_xor_sync(0xffffffffu, rs, 2, 16);
            rs += __shfl_xor_sync(0xffffffffu, rs, 4, 16);
            rs += __shfl_xor_sync(0xffffffffu, rs, 8, 16);
            l_i[i] = l_i[i] * alpha + rs;
#pragma unroll
            for (int j = 0; j < 4; j++) acc[i][j] *= alpha;
        }
#pragma unroll
        for (int j = 0; j < 4; j++) {
            float4 pv = make_float4(s[0][j], s[1][j], s[2][j], s[3][j]);
            *(float4*)&Ps[tx * 4 + j][ty * 4] = pv;
        }
        __syncthreads();
#pragma unroll
        for (int kk = 0; kk < 64; kk++) {
            float4 a = *(float4*)&Ps[kk][ty * 4];
            float4 bv4 = *(float4*)&Vs[kk][tx * 4];
            float av[4] = {a.x, a.y, a.z, a.w};
            float bv[4] = {bv4.x, bv4.y, bv4.z, bv4.w};
#pragma unroll
            for (int i = 0; i < 4; i++)
#pragma unroll
                for (int j = 0; j < 4; j++) acc[i][j] += av[i] * bv[j];
        }
        __syncthreads();
    }
    size_t obase = (size_t)(b * Lseq) * Dm + h * 64;
#pragma unroll
    for (int i = 0; i < 4; i++) {
        float inv = 1.f / l_i[i];
        float4 o = make_float4(acc[i][0] * inv, acc[i][1] * inv, acc[i][2] * inv, acc[i][3] * inv);
        *(float4*)&out[obase + (size_t)(q0 + ty * 4 + i) * Dm + tx * 4] = o;
    }
}

// ---------------- sequential delta scan ----------------
__global__ void scan_kernel(const float* __restrict__ dq, const float* __restrict__ dk,
                            const float* __restrict__ dv, const float* __restrict__ beta_pre,
                            const float* __restrict__ bbeta,
                            float* __restrict__ ys, float* __restrict__ outS,
                            float* __restrict__ outZ) {
    int bh = blockIdx.x;
    int b = bh >> 4, h = bh & 15;
    int tid = threadIdx.x;
    int r = tid >> 2, qq = tid & 3, c0 = qq * 16;
    int lane = tid & 63, g = tid >> 6;

    __shared__ float qs[64], ks[64], vs[64], zs[64];
    __shared__ float red[8];
    __shared__ float sbeta;

    float S[16];
#pragma unroll
    for (int j = 0; j < 16; j++) S[j] = 0.f;
    if (tid < 64) zs[tid] = 0.f;

    size_t rowbase = (size_t)(b * Lseq) * Dm + (size_t)h * 64;
    size_t betabase = (size_t)(b * Lseq) * Hh + h;

    float pre = 0.f;
    if (g == 0) pre = dq[rowbase + lane];
    else if (g == 1) pre = dk[rowbase + lane];
    else if (g == 2) pre = dv[rowbase + lane];
    else if (lane == 0) pre = beta_pre[betabase] + bbeta[h];

    for (int t = 0; t < Lseq; t++) {
        if (g == 0) qs[lane] = pre;
        else if (g == 1) ks[lane] = pre;
        else if (g == 2) vs[lane] = pre;
        else if (lane == 0) sbeta = 1.f / (1.f + __expf(-pre));
        __syncthreads();

        if (t + 1 < Lseq) {
            size_t row = rowbase + (size_t)(t + 1) * Dm;
            if (g == 0) pre = dq[row + lane];
            else if (g == 1) pre = dk[row + lane];
            else if (g == 2) pre = dv[row + lane];
            else if (lane == 0) pre = beta_pre[betabase + (size_t)(t + 1) * Hh] + bbeta[h];
        }

        float accy = 0.f, acco = 0.f;
#pragma unroll
        for (int j = 0; j < 16; j += 4) {
            float4 q4 = *(float4*)&qs[c0 + j];
            float4 k4 = *(float4*)&ks[c0 + j];
            accy += S[j] * q4.x + S[j + 1] * q4.y + S[j + 2] * q4.z + S[j + 3] * q4.w;
            acco += S[j] * k4.x + S[j + 1] * k4.y + S[j + 2] * k4.z + S[j + 3] * k4.w;
        }
        accy += __shfl_xor_sync(0xffffffffu, accy, 1);
        accy += __shfl_xor_sync(0xffffffffu, accy, 2);
        acco += __shfl_xor_sync(0xffffffffu, acco, 1);
        acco += __shfl_xor_sync(0xffffffffu, acco, 2);

        float dp = (tid < 64) ? zs[tid] * qs[tid] : 0.f;
#pragma unroll
        for (int off = 16; off >= 1; off >>= 1) dp += __shfl_xor_sync(0xffffffffu, dp, off);
        if ((tid & 31) == 0) red[tid >> 5] = dp;
        __syncthreads();

        float denom = red[0] + red[1] + 1e-6f;
        float bet = sbeta;
        float delta = vs[r] - acco;
        if (qq == 0) ys[rowbase + (size_t)t * Dm + r] = accy / denom;

        float bd = bet * delta;
#pragma unroll
        for (int j = 0; j < 16; j += 4) {
            float4 k4 = *(float4*)&ks[c0 + j];
            S[j] += bd * k4.x; S[j + 1] += bd * k4.y;
            S[j + 2] += bd * k4.z; S[j + 3] += bd * k4.w;
        }
        if (tid < 64) zs[tid] += bet * ks[tid];
        __syncthreads();
    }

    size_t sb = (size_t)bh * 4096;
#pragma unroll
    for (int j = 0; j < 16; j++) outS[sb + (size_t)r * 64 + c0 + j] = S[j];
    if (tid < 64) outZ[(size_t)bh * 64 + tid] = zs[tid];
}

// ---------------- layernorm ----------------
__global__ void ln_kernel(float* __restrict__ x, const float* __restrict__ gw,
                          const float* __restrict__ bw) {
    __shared__ float rs[8], rq[8];
    int row = blockIdx.x, tid = threadIdx.x;
    float* xr = x + (size_t)row * Dm;
    float4 v = *(float4*)&xr[tid * 4];
    float s = v.x + v.y + v.z + v.w;
    float s2 = v.x * v.x + v.y * v.y + v.z * v.z + v.w * v.w;
#pragma unroll
    for (int off = 16; off >= 1; off >>= 1) {
        s  += __shfl_xor_sync(0xffffffffu, s, off);
        s2 += __shfl_xor_sync(0xffffffffu, s2, off);
    }
    if ((tid & 31) == 0) { rs[tid >> 5] = s; rq[tid >> 5] = s2; }
    __syncthreads();
    float tot = 0.f, tot2 = 0.f;
#pragma unroll
    for (int w = 0; w < 8; w++) { tot += rs[w]; tot2 += rq[w]; }
    float mean = tot * (1.f / 1024.f);
    float var = tot2 * (1.f / 1024.f) - mean * mean;
    float rstd = rsqrtf(var + 1e-5f);
    float4 g4 = *(const float4*)&gw[tid * 4];
    float4 b4 = *(const float4*)&bw[tid * 4];
    v.x = (v.x - mean) * rstd * g4.x + b4.x;
    v.y = (v.y - mean) * rstd * g4.y + b4.y;
    v.z = (v.z - mean) * rstd * g4.z + b4.z;
    v.w = (v.w - mean) * rstd * g4.w + b4.w;
    *(float4*)&xr[tid * 4] = v;
}

// ---------------- final gate fusion ----------------
__global__ void gate_kernel(const float* __restrict__ gp, const float* __restrict__ bg,
                            const float* __restrict__ fl, const float* __restrict__ dl,
                            float* __restrict__ out) {
    int row = blockIdx.x, tid = threadIdx.x;
    size_t i = (size_t)row * Dm + tid * 4;
    float4 gpv = *(const float4*)&gp[i];
    float4 bgv = *(const float4*)&bg[tid * 4];
    float4 flv = *(const float4*)&fl[i];
    float4 dlv = *(const float4*)&dl[i];
    float4 o;
    {
        float g0 = 1.f / (1.f + __expf(-(gpv.x + bgv.x))); o.x = g0 * flv.x + (1.f - g0) * dlv.x;
        float g1 = 1.f / (1.f + __expf(-(gpv.y + bgv.y))); o.y = g1 * flv.y + (1.f - g1) * dlv.y;
        float g2 = 1.f / (1.f + __expf(-(gpv.z + bgv.z))); o.z = g2 * flv.z + (1.f - g2) * dlv.z;
        float g3 = 1.f / (1.f + __expf(-(gpv.w + bgv.w))); o.w = g3 * flv.w + (1.f - g3) * dlv.w;
    }
    *(float4*)&out[i] = o;
}

// ---------------- launcher ----------------
extern "C" void kernel_launch(void* const* d_in, const int* in_sizes, int n_in,
                              void* d_out, int out_size) {
    const float* x     = (const float*)d_in[0];
    const float* Wqkv  = (const float*)d_in[1];
    const float* Wout  = (const float*)d_in[2];
    const float* Wgate = (const float*)d_in[3];
    const float* bgate = (const float*)d_in[4];
    const float* fn_g  = (const float*)d_in[5];
    const float* fn_b  = (const float*)d_in[6];
    const float* dn_g  = (const float*)d_in[7];
    const float* dn_b  = (const float*)d_in[8];
    const float* dWq   = (const float*)d_in[9];
    const float* dWk   = (const float*)d_in[10];
    const float* dWv   = (const float*)d_in[11];
    const float* dWo   = (const float*)d_in[12];
    const float* Wbeta = (const float*)d_in[13];
    const float* bbeta = (const float*)d_in[14];
    const float* cq_w  = (const float*)d_in[15];
    const float* cq_b  = (const float*)d_in[16];
    const float* ck_w  = (const float*)d_in[17];
    const float* ck_b  = (const float*)d_in[18];
    const float* ln_g  = (const float*)d_in[19];
    const float* ln_b  = (const float*)d_in[20];
    float* out = (float*)d_out;

    float *p_qkv, *p_attn, *p_flash, *p_dqr, *p_dkr, *p_dq, *p_dk, *p_dv;
    float *p_beta, *p_ys, *p_delta, *p_gate;
    cudaGetSymbolAddress((void**)&p_qkv,  g_qkv);
    cudaGetSymbolAddress((void**)&p_attn, g_attn);
    cudaGetSymbolAddress((void**)&p_flash,g_flash);
    cudaGetSymbolAddress((void**)&p_dqr,  g_dqr);
    cudaGetSymbolAddress((void**)&p_dkr,  g_dkr);
    cudaGetSymbolAddress((void**)&p_dq,   g_dq);
    cudaGetSymbolAddress((void**)&p_dk,   g_dk);
    cudaGetSymbolAddress((void**)&p_dv,   g_dv);
    cudaGetSymbolAddress((void**)&p_beta, g_beta);
    cudaGetSymbolAddress((void**)&p_ys,   g_ys);
    cudaGetSymbolAddress((void**)&p_delta,g_delta);
    cudaGetSymbolAddress((void**)&p_gate, g_gate);

    float* pS = (out_size >= 4327424) ? out + 4194304 : p_qkv;
    float* pZ = (out_size >= 4327424) ? out + 4325376 : p_qkv + 4096;

    cudaFuncSetAttribute(gemm_tf32_t<false>, cudaFuncAttributeMaxDynamicSharedMemorySize, GEMM_SMEM_FAST);
    cudaFuncSetAttribute(gemm_tf32_t<true>,  cudaFuncAttributeMaxDynamicSharedMemorySize, GEMM_SMEM_P3);
    cudaFuncSetAttribute(attn_kernel, cudaFuncAttributeMaxDynamicSharedMemorySize, 65536);

    // projections: fast tf32 for damped paths, 3xTF32 for scan-sensitive paths
    gemm_tf32_t<false><<<dim3(24, 32), 256, GEMM_SMEM_FAST>>>(x, Wqkv,  p_qkv,  BL, 3 * Dm, Dm);
    gemm_tf32_t<true><<<dim3(8, 32), 256, GEMM_SMEM_P3>>>(x, dWq,   p_dqr,  BL, Dm, Dm);
    gemm_tf32_t<true><<<dim3(8, 32), 256, GEMM_SMEM_P3>>>(x, dWk,   p_dkr,  BL, Dm, Dm);
    gemm_tf32_t<true><<<dim3(8, 32), 256, GEMM_SMEM_P3>>>(x, dWv,   p_dv,   BL, Dm, Dm);
    gemm_tf32_t<false><<<dim3(8, 32), 256, GEMM_SMEM_FAST>>>(x, Wgate, p_gate, BL, Dm, Dm);
    gemm128<<<dim3(1, 32), 256>>>(x, Wbeta, p_beta, BL, Hh, Dm);

    // conv + k-normalize
    conv_kernel<<<BL, 256>>>(p_dqr, p_dkr, cq_w, cq_b, ck_w, ck_b, p_dq, p_dk);

    // flash attention
    attn_kernel<<<dim3(32, 32), 256, 65536>>>(p_qkv, p_attn);
    gemm_tf32_t<false><<<dim3(8, 32), 256, GEMM_SMEM_FAST>>>(p_attn, Wout, p_flash, BL, Dm, Dm);
    ln_kernel<<<BL, 256>>>(p_flash, fn_g, fn_b);

    // delta scan
    scan_kernel<<<32, 256>>>(p_dq, p_dk, p_dv, p_beta, bbeta, p_ys, pS, pZ);
    gemm_tf32_t<false><<<dim3(8, 32), 256, GEMM_SMEM_FAST>>>(p_ys, dWo, p_delta, BL, Dm, Dm);
    ln_kernel<<<BL, 256>>>(p_delta, ln_g, ln_b);
    ln_kernel<<<BL, 256>>>(p_delta, dn_g, dn_b);

    // gate
    gate_kernel<<<BL, 256>>>(p_gate, bgate, p_flash, p_delta, out);
}

// round 4
// speedup vs baseline: 1.5495x; 1.5495x over previous
#include <cuda_runtime.h>
#include <math.h>
#include <stdint.h>

#define Bsz 2
#define Lseq 2048
#define Dm 1024
#define Hh 16
#define HDd 64
#define BL (Bsz*Lseq)   // 4096

// ---------------- scratch (static device globals; no allocation) ----------------
__device__ float g_qkv[BL*3*Dm];
__device__ float g_attn[BL*Dm];
__device__ float g_flash[BL*Dm];
__device__ float g_dqr[BL*Dm];
__device__ float g_dkr[BL*Dm];
__device__ float g_dq[BL*Dm];
__device__ float g_dk[BL*Dm];
__device__ float g_dv[BL*Dm];
__device__ float g_beta[BL*Hh];
__device__ float g_ys[BL*Dm];
__device__ float g_delta[BL*Dm];
__device__ float g_gate[BL*Dm];

// ---------------- tf32 helpers ----------------
__device__ __forceinline__ float f2tf32(float x) {
    float r;
    asm("cvt.rna.tf32.f32 %0, %1;" : "=f"(r) : "f"(x));
    return r;
}

__device__ __forceinline__ void mma_tf32(float& c0, float& c1, float& c2, float& c3,
                                         unsigned a0, unsigned a1, unsigned a2, unsigned a3,
                                         unsigned b0, unsigned b1) {
    asm volatile("mma.sync.aligned.m16n8k8.row.col.f32.tf32.tf32.f32 "
                 "{%0,%1,%2,%3}, {%4,%5,%6,%7}, {%8,%9}, {%0,%1,%2,%3};"
                 : "+f"(c0), "+f"(c1), "+f"(c2), "+f"(c3)
                 : "r"(a0), "r"(a1), "r"(a2), "r"(a3), "r"(b0), "r"(b1));
}

// ---------------- tf32 tensor-core GEMM (optionally 3xTF32 precise) ----------------
// C[M,N] = A[M,K] @ B[K,N], row-major fp32 in/out.
// BM=128, BN=128, BK=32, 256 threads (8 warps, 2x4), warp tile 64x32.
#define AS_STRIDE 36
#define BS_STRIDE 132
#define ABUF (128*AS_STRIDE)
#define BBUF (32*BS_STRIDE)
#define GEMM_SMEM_FAST ((2*ABUF + 2*BBUF) * 4)
#define GEMM_SMEM_P3   ((4*ABUF + 4*BBUF) * 4)

template<bool P3>
__device__ __forceinline__ void stage_tile(float* Ah, float* Al, float* Bh, float* Bl,
                                           const float4* ra, const float4* rb, int tid) {
#pragma unroll
    for (int i = 0; i < 4; i++) {
        int e = tid + i * 256;
        int ar = e >> 3, ac = (e & 7) * 4;
        float* ap = &Ah[ar * AS_STRIDE + ac];
        float4 v = ra[i];
        float h0 = f2tf32(v.x), h1 = f2tf32(v.y), h2 = f2tf32(v.z), h3 = f2tf32(v.w);
        ap[0] = h0; ap[1] = h1; ap[2] = h2; ap[3] = h3;
        if (P3) {
            float* al = &Al[ar * AS_STRIDE + ac];
            al[0] = f2tf32(v.x - h0); al[1] = f2tf32(v.y - h1);
            al[2] = f2tf32(v.z - h2); al[3] = f2tf32(v.w - h3);
        }
        int br = e >> 5, bc = (e & 31) * 4;
        float4 w = rb[i];
        float g0 = f2tf32(w.x), g1 = f2tf32(w.y), g2 = f2tf32(w.z), g3 = f2tf32(w.w);
        *(float4*)&Bh[br * BS_STRIDE + bc] = make_float4(g0, g1, g2, g3);
        if (P3) {
            *(float4*)&Bl[br * BS_STRIDE + bc] =
                make_float4(f2tf32(w.x - g0), f2tf32(w.y - g1),
                            f2tf32(w.z - g2), f2tf32(w.w - g3));
        }
    }
}

template<bool P3>
__global__ void gemm_tf32_t(const float* __restrict__ A, const float* __restrict__ B,
                            float* __restrict__ C, int M, int N, int K) {
    extern __shared__ float sm[];
    float* Ah = sm;                         // [2][128][36]
    float* Bh = sm + 2 * ABUF;              // [2][32][132]
    float* Al = P3 ? sm + 2 * ABUF + 2 * BBUF : sm;
    float* Bl = P3 ? Al + 2 * ABUF : sm;

    int tid = threadIdx.x;
    int warp = tid >> 5, lane = tid & 31;
    int gid = lane >> 2, tig = lane & 3;
    int warp_m = (warp >> 2) * 64;
    int warp_n = (warp & 3) * 32;
    int m0 = blockIdx.y * 128, n0 = blockIdx.x * 128;

    float acc[4][4][4];
#pragma unroll
    for (int i = 0; i < 4; i++)
#pragma unroll
        for (int j = 0; j < 4; j++)
#pragma unroll
            for (int u = 0; u < 4; u++) acc[i][j][u] = 0.f;

    float4 ra[4], rb[4];
    int kt_total = K >> 5;

    // prologue: load tile 0
#pragma unroll
    for (int i = 0; i < 4; i++) {
        int e = tid + i * 256;
        int ar = e >> 3, ac = (e & 7) * 4;
        ra[i] = *(const float4*)&A[(size_t)(m0 + ar) * K + ac];
        int br = e >> 5, bc = (e & 31) * 4;
        rb[i] = *(const float4*)&B[(size_t)br * N + n0 + bc];
    }
    stage_tile<P3>(Ah, Al, Bh, Bl, ra, rb, tid);
    __syncthreads();

    for (int t = 0; t < kt_total; t++) {
        int cur = t & 1;
        float* Ahc = Ah + cur * ABUF;
        float* Bhc = Bh + cur * BBUF;
        float* Alc = Al + cur * ABUF;
        float* Blc = Bl + cur * BBUF;

        if (t + 1 < kt_total) {
            int kk = (t + 1) << 5;
#pragma unroll
            for (int i = 0; i < 4; i++) {
                int e = tid + i * 256;
                int ar = e >> 3, ac = (e & 7) * 4;
                ra[i] = *(const float4*)&A[(size_t)(m0 + ar) * K + kk + ac];
                int br = e >> 5, bc = (e & 31) * 4;
                rb[i] = *(const float4*)&B[(size_t)(kk + br) * N + n0 + bc];
            }
        }

#pragma unroll
        for (int ks = 0; ks < 4; ks++) {
            int k0 = ks * 8;
            unsigned afh[4][4], bfh[4][2];
            unsigned afl[4][4], bfl[4][2];
#pragma unroll
            for (int mt = 0; mt < 4; mt++) {
                int r = warp_m + mt * 16 + gid;
                const float* ap = &Ahc[r * AS_STRIDE + k0 + tig];
                afh[mt][0] = __float_as_uint(ap[0]);
                afh[mt][1] = __float_as_uint(ap[AS_STRIDE * 8]);
                afh[mt][2] = __float_as_uint(ap[4]);
                afh[mt][3] = __float_as_uint(ap[AS_STRIDE * 8 + 4]);
                if (P3) {
                    const float* al = &Alc[r * AS_STRIDE + k0 + tig];
                    afl[mt][0] = __float_as_uint(al[0]);
                    afl[mt][1] = __float_as_uint(al[AS_STRIDE * 8]);
                    afl[mt][2] = __float_as_uint(al[4]);
                    afl[mt][3] = __float_as_uint(al[AS_STRIDE * 8 + 4]);
                }
            }
#pragma unroll
            for (int nt = 0; nt < 4; nt++) {
                int c = warp_n + nt * 8 + gid;
                const float* bp = &Bhc[(k0 + tig) * BS_STRIDE + c];
                bfh[nt][0] = __float_as_uint(bp[0]);
                bfh[nt][1] = __float_as_uint(bp[BS_STRIDE * 4]);
                if (P3) {
                    const float* bl = &Blc[(k0 + tig) * BS_STRIDE + c];
                    bfl[nt][0] = __float_as_uint(bl[0]);
                    bfl[nt][1] = __float_as_uint(bl[BS_STRIDE * 4]);
                }
            }
#pragma unroll
            for (int mt = 0; mt < 4; mt++)
#pragma unroll
                for (int nt = 0; nt < 4; nt++) {
                    if (P3) {
                        mma_tf32(acc[mt][nt][0], acc[mt][nt][1], acc[mt][nt][2], acc[mt][nt][3],
                                 afh[mt][0], afh[mt][1], afh[mt][2], afh[mt][3],
                                 bfl[nt][0], bfl[nt][1]);
                        mma_tf32(acc[mt][nt][0], acc[mt][nt][1], acc[mt][nt][2], acc[mt][nt][3],
                                 afl[mt][0], afl[mt][1], afl[mt][2], afl[mt][3],
                                 bfh[nt][0], bfh[nt][1]);
                    }
                    mma_tf32(acc[mt][nt][0], acc[mt][nt][1], acc[mt][nt][2], acc[mt][nt][3],
                             afh[mt][0], afh[mt][1], afh[mt][2], afh[mt][3],
                             bfh[nt][0], bfh[nt][1]);
                }
        }

        if (t + 1 < kt_total) {
            int nxt = (t + 1) & 1;
            stage_tile<P3>(Ah + nxt * ABUF, Al + nxt * ABUF,
                           Bh + nxt * BBUF, Bl + nxt * BBUF, ra, rb, tid);
        }
        __syncthreads();
    }

    // epilogue
#pragma unroll
    for (int mt = 0; mt < 4; mt++) {
#pragma unroll
        for (int nt = 0; nt < 4; nt++) {
            int row = m0 + warp_m + mt * 16 + gid;
            int col = n0 + warp_n + nt * 8 + 2 * tig;
            *(float2*)&C[(size_t)row * N + col] =
                make_float2(acc[mt][nt][0], acc[mt][nt][1]);
            *(float2*)&C[(size_t)(row + 8) * N + col] =
                make_float2(acc[mt][nt][2], acc[mt][nt][3]);
        }
    }
}

// ---------------- small SGEMM (for Wbeta, N=16) ----------------
__global__ void gemm128(const float* __restrict__ A, const float* __restrict__ Bm,
                        float* __restrict__ C, int M, int N, int K) {
    __shared__ float As[16][128];
    __shared__ float Bs[16][64];
    int tid = threadIdx.x;
    int tx = tid & 15, ty = tid >> 4;
    int m0 = blockIdx.y * 128, n0 = blockIdx.x * 64;

    int arow = tid >> 2;
    int ak4  = (tid & 3) * 4;
    int brow = tid >> 4;
    int bc4  = (tid & 15) * 4;

    float acc[8][4];
#pragma unroll
    for (int i = 0; i < 8; i++)
#pragma unroll
        for (int j = 0; j < 4; j++) acc[i][j] = 0.f;

    for (int kk = 0; kk < K; kk += 16) {
#pragma unroll
        for (int half = 0; half < 2; half++) {
            int r = arow + half * 64;
            float4 a4 = *(const float4*)&A[(size_t)(m0 + r) * K + kk + ak4];
            As[ak4 + 0][r] = a4.x; As[ak4 + 1][r] = a4.y;
            As[ak4 + 2][r] = a4.z; As[ak4 + 3][r] = a4.w;
        }
        if (n0 + bc4 < N) {
            *(float4*)&Bs[brow][bc4] = *(const float4*)&Bm[(size_t)(kk + brow) * N + n0 + bc4];
        } else {
            *(float4*)&Bs[brow][bc4] = make_float4(0.f, 0.f, 0.f, 0.f);
        }
        __syncthreads();
#pragma unroll
        for (int k2 = 0; k2 < 16; k2++) {
            float4 b4 = *(float4*)&Bs[k2][tx * 4];
            float4 aa = *(float4*)&As[k2][ty * 8];
            float4 ab = *(float4*)&As[k2][ty * 8 + 4];
            float av[8] = {aa.x, aa.y, aa.z, aa.w, ab.x, ab.y, ab.z, ab.w};
            float bv[4] = {b4.x, b4.y, b4.z, b4.w};
#pragma unroll
            for (int i = 0; i < 8; i++)
#pragma unroll
                for (int j = 0; j < 4; j++) acc[i][j] += av[i] * bv[j];
        }
        __syncthreads();
    }
    if (n0 + tx * 4 < N) {
#pragma unroll
        for (int i = 0; i < 8; i++) {
            int row = m0 + ty * 8 + i;
            float4 o = make_float4(acc[i][0], acc[i][1], acc[i][2], acc[i][3]);
            *(float4*)&C[(size_t)row * N + n0 + tx * 4] = o;
        }
    }
}

// ---------------- conv (causal depthwise, KW=4) + k-normalization ----------------
__global__ void conv_kernel(const float* __restrict__ dqr, const float* __restrict__ dkr,
                            const float* __restrict__ cqw, const float* __restrict__ cqb,
                            const float* __restrict__ ckw, const float* __restrict__ ckb,
                            float* __restrict__ dq, float* __restrict__ dk) {
    int bt = blockIdx.x;
    int t  = bt & (Lseq - 1);
    int tid = threadIdx.x;
    int c0 = tid * 4;

    float xq[4][4], xk[4][4];
#pragma unroll
    for (int j = 0; j < 4; j++) {
        int tt = t - 3 + j;
        if (tt >= 0) {
            float4 a = *(const float4*)&dqr[(size_t)(bt - 3 + j) * Dm + c0];
            xq[j][0] = a.x; xq[j][1] = a.y; xq[j][2] = a.z; xq[j][3] = a.w;
            float4 b = *(const float4*)&dkr[(size_t)(bt - 3 + j) * Dm + c0];
            xk[j][0] = b.x; xk[j][1] = b.y; xk[j][2] = b.z; xk[j][3] = b.w;
        } else {
#pragma unroll
            for (int u = 0; u < 4; u++) { xq[j][u] = 0.f; xk[j][u] = 0.f; }
        }
    }
    float4 qb4 = *(const float4*)&cqb[c0];
    float4 kb4 = *(const float4*)&ckb[c0];
    float qbv[4] = {qb4.x, qb4.y, qb4.z, qb4.w};
    float kbv[4] = {kb4.x, kb4.y, kb4.z, kb4.w};

    float oq[4], ok[4];
#pragma unroll
    for (int u = 0; u < 4; u++) {
        float4 wq = *(const float4*)&cqw[(c0 + u) * 4];
        float4 wk = *(const float4*)&ckw[(c0 + u) * 4];
        oq[u] = qbv[u] + wq.x * xq[0][u] + wq.y * xq[1][u] + wq.z * xq[2][u] + wq.w * xq[3][u];
        ok[u] = kbv[u] + wk.x * xk[0][u] + wk.y * xk[1][u] + wk.z * xk[2][u] + wk.w * xk[3][u];
    }
    *(float4*)&dq[(size_t)bt * Dm + c0] = make_float4(oq[0], oq[1], oq[2], oq[3]);

    float ss = ok[0] * ok[0] + ok[1] * ok[1] + ok[2] * ok[2] + ok[3] * ok[3];
    ss += __shfl_xor_sync(0xffffffffu, ss, 1, 16);
    ss += __shfl_xor_sync(0xffffffffu, ss, 2, 16);
    ss += __shfl_xor_sync(0xffffffffu, ss, 4, 16);
    ss += __shfl_xor_sync(0xffffffffu, ss, 8, 16);
    float rn = 1.f / fmaxf(sqrtf(ss), 1e-12f);
    *(float4*)&dk[(size_t)bt * Dm + c0] =
        make_float4(ok[0] * rn, ok[1] * rn, ok[2] * rn, ok[3] * rn);
}

// ---------------- causal flash attention (fp32, streaming) ----------------
__global__ void attn_kernel(const float* __restrict__ qkv, float* __restrict__ out) {
    extern __shared__ float sm[];
    float (*Qs)[64] = (float(*)[64])(sm);
    float (*Ks)[64] = (float(*)[64])(sm + 4096);
    float (*Vs)[64] = (float(*)[64])(sm + 8192);
    float (*Ps)[64] = (float(*)[64])(sm + 12288);

    int qt = blockIdx.x, bh = blockIdx.y;
    int b = bh >> 4, h = bh & 15;
    int tid = threadIdx.x;
    int tx = tid & 15, ty = tid >> 4;
    int q0 = qt * 64;
    size_t qkvbase = (size_t)(b * Lseq) * 3072 + h * 64;

    int lr = tid >> 2;
    int ldb = (tid & 3) * 16;

#pragma unroll
    for (int i = 0; i < 16; i += 4) {
        float4 a = *(const float4*)&qkv[qkvbase + (size_t)(q0 + lr) * 3072 + ldb + i];
        Qs[ldb + i + 0][lr] = a.x; Qs[ldb + i + 1][lr] = a.y;
        Qs[ldb + i + 2][lr] = a.z; Qs[ldb + i + 3][lr] = a.w;
    }

    float acc[4][4];
    float m_i[4], l_i[4];
#pragma unroll
    for (int i = 0; i < 4; i++) {
        m_i[i] = -1e30f; l_i[i] = 0.f;
#pragma unroll
        for (int j = 0; j < 4; j++) acc[i][j] = 0.f;
    }
    __syncthreads();

    for (int kt = 0; kt <= qt; kt++) {
        int k0 = kt * 64;
#pragma unroll
        for (int i = 0; i < 16; i += 4) {
            float4 a = *(const float4*)&qkv[qkvbase + 1024 + (size_t)(k0 + lr) * 3072 + ldb + i];
            Ks[ldb + i + 0][lr] = a.x; Ks[ldb + i + 1][lr] = a.y;
            Ks[ldb + i + 2][lr] = a.z; Ks[ldb + i + 3][lr] = a.w;
            float4 v = *(const float4*)&qkv[qkvbase + 2048 + (size_t)(k0 + lr) * 3072 + ldb + i];
            *(float4*)&Vs[lr][ldb + i] = v;
        }
        __syncthreads();

        float s[4][4];
#pragma unroll
        for (int i = 0; i < 4; i++)
#pragma unroll
            for (int j = 0; j < 4; j++) s[i][j] = 0.f;
#pragma unroll
        for (int d = 0; d < 64; d++) {
            float4 a = *(float4*)&Qs[d][ty * 4];
            float4 bq = *(float4*)&Ks[d][tx * 4];
            float av[4] = {a.x, a.y, a.z, a.w};
            float bv[4] = {bq.x, bq.y, bq.z, bq.w};
#pragma unroll
            for (int i = 0; i < 4; i++)
#pragma unroll
                for (int j = 0; j < 4; j++) s[i][j] += av[i] * bv[j];
        }
        if (kt == qt) {
#pragma unroll
            for (int i = 0; i < 4; i++)
#pragma unroll
                for (int j = 0; j < 4; j++) {
                    if (tx * 4 + j > ty * 4 + i) s[i][j] = -1e30f;
                    else s[i][j] *= 0.125f;
                }
        } else {
#pragma unroll
            for (int i = 0; i < 4; i++)
#pragma unroll
                for (int j = 0; j < 4; j++) s[i][j] *= 0.125f;
        }
#pragma unroll
        for (int i = 0; i < 4; i++) {
            float mm = fmaxf(fmaxf(s[i][0], s[i][1]), fmaxf(s[i][2], s[i][3]));
            mm = fmaxf(mm, __shfl_xor_sync(0xffffffffu, mm, 1, 16));
            mm = fmaxf(mm, __shfl_xor_sync(0xffffffffu, mm, 2, 16));
            mm = fmaxf(mm, __shfl_xor_sync(0xffffffffu, mm, 4, 16));
            mm = fmaxf(mm, __shfl_xor_sync(0xffffffffu, mm, 8, 16));
            float mt = fmaxf(m_i[i], mm);
            float alpha = __expf(m_i[i] - mt);
            m_i[i] = mt;
            float rs = 0.f;
#pragma unroll
            for (int j = 0; j < 4; j++) { s[i][j] = __expf(s[i][j] - mt); rs += s[i][j]; }
            rs += __shfl_xor_sync(0xffffffffu, rs, 1, 16);
            rs += __shfl_xor_sync(0xffffffffu, rs, 2, 16);
            rs += __shfl_xor_sync(0xffffffffu, rs, 4, 16);
            rs += __shfl_xor_sync(0xffffffffu, rs, 8, 16);
            l_i[i] = l_i[i] * alpha + rs;
#pragma unroll
            for (int j = 0; j < 4; j++) acc[i][j] *= alpha;
        }
#pragma unroll
        for (int j = 0; j < 4; j++) {
            float4 pv = make_float4(s[0][j], s[1][j], s[2][j], s[3][j]);
            *(float4*)&Ps[tx * 4 + j][ty * 4] = pv;
        }
        __syncthreads();
#pragma unroll
        for (int kk = 0; kk < 64; kk++) {
            float4 a = *(float4*)&Ps[kk][ty * 4];
            float4 bv4 = *(float4*)&Vs[kk][tx * 4];
            float av[4] = {a.x, a.y, a.z, a.w};
            float bv[4] = {bv4.x, bv4.y, bv4.z, bv4.w};
#pragma unroll
            for (int i = 0; i < 4; i++)
#pragma unroll
                for (int j = 0; j < 4; j++) acc[i][j] += av[i] * bv[j];
        }
        __syncthreads();
    }
    size_t obase = (size_t)(b * Lseq) * Dm + h * 64;
#pragma unroll
    for (int i = 0; i < 4; i++) {
        float inv = 1.f / l_i[i];
        float4 o = make_float4(acc[i][0] * inv, acc[i][1] * inv, acc[i][2] * inv, acc[i][3] * inv);
        *(float4*)&out[obase + (size_t)(q0 + ty * 4 + i) * Dm + tx * 4] = o;
    }
}

// ---------------- sequential delta scan ----------------
__global__ void scan_kernel(const float* __restrict__ dq, const float* __restrict__ dk,
                            const float* __restrict__ dv, const float* __restrict__ beta_pre,
                            const float* __restrict__ bbeta,
                            float* __restrict__ ys, float* __restrict__ outS,
                            float* __restrict__ outZ) {
    int bh = blockIdx.x;
    int b = bh >> 4, h = bh & 15;
    int tid = threadIdx.x;
    int r = tid >> 2, qq = tid & 3, c0 = qq * 16;
    int lane = tid & 63, g = tid >> 6;

    __shared__ float qs[64], ks[64], vs[64], zs[64];
    __shared__ float red[8];
    __shared__ float sbeta;

    float S[16];
#pragma unroll
    for (int j = 0; j < 16; j++) S[j] = 0.f;
    if (tid < 64) zs[tid] = 0.f;

    size_t rowbase = (size_t)(b * Lseq) * Dm + (size_t)h * 64;
    size_t betabase = (size_t)(b * Lseq) * Hh + h;

    float pre = 0.f;
    if (g == 0) pre = dq[rowbase + lane];
    else if (g == 1) pre = dk[rowbase + lane];
    else if (g == 2) pre = dv[rowbase + lane];
    else if (lane == 0) pre = beta_pre[betabase] + bbeta[h];

    for (int t = 0; t < Lseq; t++) {
        if (g == 0) qs[lane] = pre;
        else if (g == 1) ks[lane] = pre;
        else if (g == 2) vs[lane] = pre;
        else if (lane == 0) sbeta = 1.f / (1.f + __expf(-pre));
        __syncthreads();

        if (t + 1 < Lseq) {
            size_t row = rowbase + (size_t)(t + 1) * Dm;
            if (g == 0) pre = dq[row + lane];
            else if (g == 1) pre = dk[row + lane];
            else if (g == 2) pre = dv[row + lane];
            else if (lane == 0) pre = beta_pre[betabase + (size_t)(t + 1) * Hh] + bbeta[h];
        }

        float accy = 0.f, acco = 0.f;
#pragma unroll
        for (int j = 0; j < 16; j += 4) {
            float4 q4 = *(float4*)&qs[c0 + j];
            float4 k4 = *(float4*)&ks[c0 + j];
            accy += S[j] * q4.x + S[j + 1] * q4.y + S[j + 2] * q4.z + S[j + 3] * q4.w;
            acco += S[j] * k4.x + S[j + 1] * k4.y + S[j + 2] * k4.z + S[j + 3] * k4.w;
        }
        accy += __shfl_xor_sync(0xffffffffu, accy, 1);
        accy += __shfl_xor_sync(0xffffffffu, accy, 2);
        acco += __shfl_xor_sync(0xffffffffu, acco, 1);
        acco += __shfl_xor_sync(0xffffffffu, acco, 2);

        float dp = (tid < 64) ? zs[tid] * qs[tid] : 0.f;
#pragma unroll
        for (int off = 16; off >= 1; off >>= 1) dp += __shfl_xor_sync(0xffffffffu, dp, off);
        if ((tid & 31) == 0) red[tid >> 5] = dp;
        __syncthreads();

        float denom = red[0] + red[1] + 1e-6f;
        float bet = sbeta;
        float delta = vs[r] - acco;
        if (qq == 0) ys[rowbase + (size_t)t * Dm + r] = accy / denom;

        float bd = bet * delta;
#pragma unroll
        for (int j = 0; j < 16; j += 4) {
            float4 k4 = *(float4*)&ks[c0 + j];
            S[j] += bd * k4.x; S[j + 1] += bd * k4.y;
            S[j + 2] += bd * k4.z; S[j + 3] += bd * k4.w;
        }
        if (tid < 64) zs[tid] += bet * ks[tid];
        __syncthreads();
    }

    size_t sb = (size_t)bh * 4096;
#pragma unroll
    for (int j = 0; j < 16; j++) outS[sb + (size_t)r * 64 + c0 + j] = S[j];
    if (tid < 64) outZ[(size_t)bh * 64 + tid] = zs[tid];
}

// ---------------- layernorm ----------------
__global__ void ln_kernel(float* __restrict__ x, const float* __restrict__ gw,
                          const float* __restrict__ bw) {
    __shared__ float rs[8], rq[8];
    int row = blockIdx.x, tid = threadIdx.x;
    float* xr = x + (size_t)row * Dm;
    float4 v = *(float4*)&xr[tid * 4];
    float s = v.x + v.y + v.z + v.w;
    float s2 = v.x * v.x + v.y * v.y + v.z * v.z + v.w * v.w;
#pragma unroll
    for (int off = 16; off >= 1; off >>= 1) {
        s  += __shfl_xor_sync(0xffffffffu, s, off);
        s2 += __shfl_xor_sync(0xffffffffu, s2, off);
    }
    if ((tid & 31) == 0) { rs[tid >> 5] = s; rq[tid >> 5] = s2; }
    __syncthreads();
    float tot = 0.f, tot2 = 0.f;
#pragma unroll
    for (int w = 0; w < 8; w++) { tot += rs[w]; tot2 += rq[w]; }
    float mean = tot * (1.f / 1024.f);
    float var = tot2 * (1.f / 1024.f) - mean * mean;
    float rstd = rsqrtf(var + 1e-5f);
    float4 g4 = *(const float4*)&gw[tid * 4];
    float4 b4 = *(const float4*)&bw[tid * 4];
    v.x = (v.x - mean) * rstd * g4.x + b4.x;
    v.y = (v.y - mean) * rstd * g4.y + b4.y;
    v.z = (v.z - mean) * rstd * g4.z + b4.z;
    v.w = (v.w - mean) * rstd * g4.w + b4.w;
    *(float4*)&xr[tid * 4] = v;
}

// ---------------- final gate fusion ----------------
__global__ void gate_kernel(const float* __restrict__ gp, const float* __restrict__ bg,
                            const float* __restrict__ fl, const float* __restrict__ dl,
                            float* __restrict__ out) {
    int row = blockIdx.x, tid = threadIdx.x;
    size_t i = (size_t)row * Dm + tid * 4;
    float4 gpv = *(const float4*)&gp[i];
    float4 bgv = *(const float4*)&bg[tid * 4];
    float4 flv = *(const float4*)&fl[i];
    float4 dlv = *(const float4*)&dl[i];
    float4 o;
    {
        float g0 = 1.f / (1.f + __expf(-(gpv.x + bgv.x))); o.x = g0 * flv.x + (1.f - g0) * dlv.x;
        float g1 = 1.f / (1.f + __expf(-(gpv.y + bgv.y))); o.y = g1 * flv.y + (1.f - g1) * dlv.y;
        float g2 = 1.f / (1.f + __expf(-(gpv.z + bgv.z))); o.z = g2 * flv.z + (1.f - g2) * dlv.z;
        float g3 = 1.f / (1.f + __expf(-(gpv.w + bgv.w))); o.w = g3 * flv.w + (1.f - g3) * dlv.w;
    }
    *(float4*)&out[i] = o;
}

// ---------------- launcher ----------------
extern "C" void kernel_launch(void* const* d_in, const int* in_sizes, int n_in,
                              void* d_out, int out_size) {
    const float* x     = (const float*)d_in[0];
    const float* Wqkv  = (const float*)d_in[1];
    const float* Wout  = (const float*)d_in[2];
    const float* Wgate = (const float*)d_in[3];
    const float* bgate = (const float*)d_in[4];
    const float* fn_g  = (const float*)d_in[5];
    const float* fn_b  = (const float*)d_in[6];
    const float* dn_g  = (const float*)d_in[7];
    const float* dn_b  = (const float*)d_in[8];
    const float* dWq   = (const float*)d_in[9];
    const float* dWk   = (const float*)d_in[10];
    const float* dWv   = (const float*)d_in[11];
    const float* dWo   = (const float*)d_in[12];
    const float* Wbeta = (const float*)d_in[13];
    const float* bbeta = (const float*)d_in[14];
    const float* cq_w  = (const float*)d_in[15];
    const float* cq_b  = (const float*)d_in[16];
    const float* ck_w  = (const float*)d_in[17];
    const float* ck_b  = (const float*)d_in[18];
    const float* ln_g  = (const float*)d_in[19];
    const float* ln_b  = (const float*)d_in[20];
    float* out = (float*)d_out;

    float *p_qkv, *p_attn, *p_flash, *p_dqr, *p_dkr, *p_dq, *p_dk, *p_dv;
    float *p_beta, *p_ys, *p_delta, *p_gate;
    cudaGetSymbolAddress((void**)&p_qkv,  g_qkv);
    cudaGetSymbolAddress((void**)&p_attn, g_attn);
    cudaGetSymbolAddress((void**)&p_flash,g_flash);
    cudaGetSymbolAddress((void**)&p_dqr,  g_dqr);
    cudaGetSymbolAddress((void**)&p_dkr,  g_dkr);
    cudaGetSymbolAddress((void**)&p_dq,   g_dq);
    cudaGetSymbolAddress((void**)&p_dk,   g_dk);
    cudaGetSymbolAddress((void**)&p_dv,   g_dv);
    cudaGetSymbolAddress((void**)&p_beta, g_beta);
    cudaGetSymbolAddress((void**)&p_ys,   g_ys);
    cudaGetSymbolAddress((void**)&p_delta,g_delta);
    cudaGetSymbolAddress((void**)&p_gate, g_gate);

    float* pS = (out_size >= 4327424) ? out + 4194304 : p_qkv;
    float* pZ = (out_size >= 4327424) ? out + 4325376 : p_qkv + 4096;

    cudaFuncSetAttribute(gemm_tf32_t<false>, cudaFuncAttributeMaxDynamicSharedMemorySize, GEMM_SMEM_FAST);
    cudaFuncSetAttribute(gemm_tf32_t<true>,  cudaFuncAttributeMaxDynamicSharedMemorySize, GEMM_SMEM_P3);
    cudaFuncSetAttribute(attn_kernel, cudaFuncAttributeMaxDynamicSharedMemorySize, 65536);

    // projections: fast tf32 for damped paths, 3xTF32 for scan-sensitive paths
    gemm_tf32_t<false><<<dim3(24, 32), 256, GEMM_SMEM_FAST>>>(x, Wqkv,  p_qkv,  BL, 3 * Dm, Dm);
    gemm_tf32_t<true><<<dim3(8, 32), 256, GEMM_SMEM_P3>>>(x, dWq,   p_dqr,  BL, Dm, Dm);
    gemm_tf32_t<true><<<dim3(8, 32), 256, GEMM_SMEM_P3>>>(x, dWk,   p_dkr,  BL, Dm, Dm);
    gemm_tf32_t<true><<<dim3(8, 32), 256, GEMM_SMEM_P3>>>(x, dWv,   p_dv,   BL, Dm, Dm);
    gemm_tf32_t<false><<<dim3(8, 32), 256, GEMM_SMEM_FAST>>>(x, Wgate, p_gate, BL, Dm, Dm);
    gemm128<<<dim3(1, 32), 256>>>(x, Wbeta, p_beta, BL, Hh, Dm);

    // conv + k-normalize
    conv_kernel<<<BL, 256>>>(p_dqr, p_dkr, cq_w, cq_b, ck_w, ck_b, p_dq, p_dk);

    // flash attention
    attn_kernel<<<dim3(32, 32), 256, 65536>>>(p_qkv, p_attn);
    gemm_tf32_t<false><<<dim3(8, 32), 256, GEMM_SMEM_FAST>>>(p_attn, Wout, p_flash, BL, Dm, Dm);
    ln_kernel<<<BL, 256>>>(p_flash, fn_g, fn_b);

    // delta scan
    scan_kernel<<<32, 256>>>(p_dq, p_dk, p_dv, p_beta, bbeta, p_ys, pS, pZ);
    gemm_tf32_t<false><<<dim3(8, 32), 256, GEMM_SMEM_FAST>>>(p_ys, dWo, p_delta, BL, Dm, Dm);
    ln_kernel<<<BL, 256>>>(p_delta, ln_g, ln_b);
    ln_kernel<<<BL, 256>>>(p_delta, dn_g, dn_b);

    // gate
    gate_kernel<<<BL, 256>>>(p_gate, bgate, p_flash, p_delta, out);
}

// round 6
// speedup vs baseline: 1.6107x; 1.0395x over previous
#include <cuda_runtime.h>
#include <math.h>
#include <stdint.h>

#define Bsz 2
#define Lseq 2048
#define Dm 1024
#define Hh 16
#define BL (Bsz*Lseq)   // 4096

// ---------------- scratch ----------------
__device__ float g_qkv[BL*3*Dm];
__device__ float g_attn[BL*Dm];
__device__ float g_flash[BL*Dm];
__device__ float g_dqr[BL*Dm];
__device__ float g_dkr[BL*Dm];
__device__ float g_dq[BL*Dm];
__device__ float g_dk[BL*Dm];
__device__ float g_dv[BL*Dm];
__device__ float g_beta[BL*Hh];
__device__ float g_ys[BL*Dm];
__device__ float g_delta[BL*Dm];
__device__ float g_gate[BL*Dm];

// ---------------- tf32 helpers ----------------
__device__ __forceinline__ float f2tf32(float x) {
    float r;
    asm("cvt.rna.tf32.f32 %0, %1;" : "=f"(r) : "f"(x));
    return r;
}
__device__ __forceinline__ void mma_tf32(float& c0, float& c1, float& c2, float& c3,
                                         unsigned a0, unsigned a1, unsigned a2, unsigned a3,
                                         unsigned b0, unsigned b1) {
    asm volatile("mma.sync.aligned.m16n8k8.row.col.f32.tf32.tf32.f32 "
                 "{%0,%1,%2,%3}, {%4,%5,%6,%7}, {%8,%9}, {%0,%1,%2,%3};"
                 : "+f"(c0), "+f"(c1), "+f"(c2), "+f"(c3)
                 : "r"(a0), "r"(a1), "r"(a2), "r"(a3), "r"(b0), "r"(b1));
}

// ---------------- tf32 tensor-core GEMM (optionally 3xTF32 precise) ----------------
#define AS_STRIDE 36
#define BS_STRIDE 132
#define ABUF (128*AS_STRIDE)
#define BBUF (32*BS_STRIDE)
#define GEMM_SMEM_FAST ((2*ABUF + 2*BBUF) * 4)
#define GEMM_SMEM_P3   ((4*ABUF + 4*BBUF) * 4)

template<bool P3>
__device__ __forceinline__ void stage_tile(float* Ah, float* Al, float* Bh, float* Bl,
                                           const float4* ra, const float4* rb, int tid) {
#pragma unroll
    for (int i = 0; i < 4; i++) {
        int e = tid + i * 256;
        int ar = e >> 3, ac = (e & 7) * 4;
        float* ap = &Ah[ar * AS_STRIDE + ac];
        float4 v = ra[i];
        float h0 = f2tf32(v.x), h1 = f2tf32(v.y), h2 = f2tf32(v.z), h3 = f2tf32(v.w);
        ap[0] = h0; ap[1] = h1; ap[2] = h2; ap[3] = h3;
        if (P3) {
            float* al = &Al[ar * AS_STRIDE + ac];
            al[0] = f2tf32(v.x - h0); al[1] = f2tf32(v.y - h1);
            al[2] = f2tf32(v.z - h2); al[3] = f2tf32(v.w - h3);
        }
        int br = e >> 5, bc = (e & 31) * 4;
        float4 w = rb[i];
        float g0 = f2tf32(w.x), g1 = f2tf32(w.y), g2 = f2tf32(w.z), g3 = f2tf32(w.w);
        *(float4*)&Bh[br * BS_STRIDE + bc] = make_float4(g0, g1, g2, g3);
        if (P3) {
            *(float4*)&Bl[br * BS_STRIDE + bc] =
                make_float4(f2tf32(w.x - g0), f2tf32(w.y - g1),
                            f2tf32(w.z - g2), f2tf32(w.w - g3));
        }
    }
}

template<bool P3>
__global__ void gemm_tf32_t(const float* __restrict__ A, const float* __restrict__ B,
                            float* __restrict__ C, int M, int N, int K) {
    extern __shared__ float sm[];
    float* Ah = sm;
    float* Bh = sm + 2 * ABUF;
    float* Al = P3 ? sm + 2 * ABUF + 2 * BBUF : sm;
    float* Bl = P3 ? Al + 2 * ABUF : sm;

    int tid = threadIdx.x;
    int warp = tid >> 5, lane = tid & 31;
    int gid = lane >> 2, tig = lane & 3;
    int warp_m = (warp >> 2) * 64;
    int warp_n = (warp & 3) * 32;
    int m0 = blockIdx.y * 128, n0 = blockIdx.x * 128;

    float acc[4][4][4];
#pragma unroll
    for (int i = 0; i < 4; i++)
#pragma unroll
        for (int j = 0; j < 4; j++)
#pragma unroll
            for (int u = 0; u < 4; u++) acc[i][j][u] = 0.f;

    float4 ra[4], rb[4];
    int kt_total = K >> 5;

#pragma unroll
    for (int i = 0; i < 4; i++) {
        int e = tid + i * 256;
        int ar = e >> 3, ac = (e & 7) * 4;
        ra[i] = *(const float4*)&A[(size_t)(m0 + ar) * K + ac];
        int br = e >> 5, bc = (e & 31) * 4;
        rb[i] = *(const float4*)&B[(size_t)br * N + n0 + bc];
    }
    stage_tile<P3>(Ah, Al, Bh, Bl, ra, rb, tid);
    __syncthreads();

    for (int t = 0; t < kt_total; t++) {
        int cur = t & 1;
        float* Ahc = Ah + cur * ABUF;
        float* Bhc = Bh + cur * BBUF;
        float* Alc = Al + cur * ABUF;
        float* Blc = Bl + cur * BBUF;

        if (t + 1 < kt_total) {
            int kk = (t + 1) << 5;
#pragma unroll
            for (int i = 0; i < 4; i++) {
                int e = tid + i * 256;
                int ar = e >> 3, ac = (e & 7) * 4;
                ra[i] = *(const float4*)&A[(size_t)(m0 + ar) * K + kk + ac];
                int br = e >> 5, bc = (e & 31) * 4;
                rb[i] = *(const float4*)&B[(size_t)(kk + br) * N + n0 + bc];
            }
        }

#pragma unroll
        for (int ks = 0; ks < 4; ks++) {
            int k0 = ks * 8;
            unsigned afh[4][4], bfh[4][2];
            unsigned afl[4][4], bfl[4][2];
#pragma unroll
            for (int mt = 0; mt < 4; mt++) {
                int r = warp_m + mt * 16 + gid;
                const float* ap = &Ahc[r * AS_STRIDE + k0 + tig];
                afh[mt][0] = __float_as_uint(ap[0]);
                afh[mt][1] = __float_as_uint(ap[AS_STRIDE * 8]);
                afh[mt][2] = __float_as_uint(ap[4]);
                afh[mt][3] = __float_as_uint(ap[AS_STRIDE * 8 + 4]);
                if (P3) {
                    const float* al = &Alc[r * AS_STRIDE + k0 + tig];
                    afl[mt][0] = __float_as_uint(al[0]);
                    afl[mt][1] = __float_as_uint(al[AS_STRIDE * 8]);
                    afl[mt][2] = __float_as_uint(al[4]);
                    afl[mt][3] = __float_as_uint(al[AS_STRIDE * 8 + 4]);
                }
            }
#pragma unroll
            for (int nt = 0; nt < 4; nt++) {
                int c = warp_n + nt * 8 + gid;
                const float* bp = &Bhc[(k0 + tig) * BS_STRIDE + c];
                bfh[nt][0] = __float_as_uint(bp[0]);
                bfh[nt][1] = __float_as_uint(bp[BS_STRIDE * 4]);
                if (P3) {
                    const float* bl = &Blc[(k0 + tig) * BS_STRIDE + c];
                    bfl[nt][0] = __float_as_uint(bl[0]);
                    bfl[nt][1] = __float_as_uint(bl[BS_STRIDE * 4]);
                }
            }
#pragma unroll
            for (int mt = 0; mt < 4; mt++)
#pragma unroll
                for (int nt = 0; nt < 4; nt++) {
                    if (P3) {
                        mma_tf32(acc[mt][nt][0], acc[mt][nt][1], acc[mt][nt][2], acc[mt][nt][3],
                                 afh[mt][0], afh[mt][1], afh[mt][2], afh[mt][3],
                                 bfl[nt][0], bfl[nt][1]);
                        mma_tf32(acc[mt][nt][0], acc[mt][nt][1], acc[mt][nt][2], acc[mt][nt][3],
                                 afl[mt][0], afl[mt][1], afl[mt][2], afl[mt][3],
                                 bfh[nt][0], bfh[nt][1]);
                    }
                    mma_tf32(acc[mt][nt][0], acc[mt][nt][1], acc[mt][nt][2], acc[mt][nt][3],
                             afh[mt][0], afh[mt][1], afh[mt][2], afh[mt][3],
                             bfh[nt][0], bfh[nt][1]);
                }
        }

        if (t + 1 < kt_total) {
            int nxt = (t + 1) & 1;
            stage_tile<P3>(Ah + nxt * ABUF, Al + nxt * ABUF,
                           Bh + nxt * BBUF, Bl + nxt * BBUF, ra, rb, tid);
        }
        __syncthreads();
    }

#pragma unroll
    for (int mt = 0; mt < 4; mt++) {
#pragma unroll
        for (int nt = 0; nt < 4; nt++) {
            int row = m0 + warp_m + mt * 16 + gid;
            int col = n0 + warp_n + nt * 8 + 2 * tig;
            *(float2*)&C[(size_t)row * N + col] =
                make_float2(acc[mt][nt][0], acc[mt][nt][1]);
            *(float2*)&C[(size_t)(row + 8) * N + col] =
                make_float2(acc[mt][nt][2], acc[mt][nt][3]);
        }
    }
}

// ---------------- mma-based causal flash attention ----------------
// Q-block 128 rows per CTA, K-tiles of 64. 8 warps, each owns 16 q-rows.
// QK^T and P*V both 3xTF32. K staged transposed [d][key]; V natural [key][d].
#define AST 68
#define ATTN_SMEM (52224 * 4)

__global__ void __launch_bounds__(256, 1) attn_mma(const float* __restrict__ qkv,
                                                   float* __restrict__ out) {
    extern __shared__ float sm[];
    float* Qh  = sm;            // [128][68]
    float* Ql  = sm + 8704;
    float* Kth = sm + 17408;    // [64][68]  (d, key)
    float* Ktl = sm + 21760;
    float* Vh  = sm + 26112;    // [64][68]  (key, d)
    float* Vl  = sm + 30464;
    float* Ph  = sm + 34816;    // [128][68]
    float* Pl  = sm + 43520;

    int qb = blockIdx.x, bh = blockIdx.y;
    int b = bh >> 4, h = bh & 15;
    int tid = threadIdx.x, warp = tid >> 5, lane = tid & 31;
    int gid = lane >> 2, tig = lane & 3;
    size_t base = (size_t)(b * Lseq) * 3072 + h * 64;
    int q0 = qb * 128;
    int row_lo = warp * 16 + gid;   // local q row for c0,c1 (+8 for c2,c3)

    // stage Q (split)
    {
        int r = tid >> 1, dc = (tid & 1) * 32;
        const float* src = &qkv[base + (size_t)(q0 + r) * 3072 + dc];
        float* qh = &Qh[r * AST + dc];
        float* ql = &Ql[r * AST + dc];
#pragma unroll
        for (int i = 0; i < 32; i += 4) {
            float4 v = *(const float4*)&src[i];
            float h0 = f2tf32(v.x), h1 = f2tf32(v.y), h2 = f2tf32(v.z), h3 = f2tf32(v.w);
            *(float4*)&qh[i] = make_float4(h0, h1, h2, h3);
            *(float4*)&ql[i] = make_float4(f2tf32(v.x - h0), f2tf32(v.y - h1),
                                           f2tf32(v.z - h2), f2tf32(v.w - h3));
        }
    }
    float acc[8][4];
#pragma unroll
    for (int nt = 0; nt < 8; nt++)
#pragma unroll
        for (int cc = 0; cc < 4; cc++) acc[nt][cc] = 0.f;
    float m0 = -1e30f, m1 = -1e30f, l0 = 0.f, l1 = 0.f;
    __syncthreads();

    int ktend = 2 * qb + 1;
    for (int kt = 0; kt <= ktend; kt++) {
        int k0 = kt * 64;
        // stage K transposed + V natural (split)
        {
            int r = tid >> 2, dc = (tid & 3) * 16;
            const float* ks = &qkv[base + 1024 + (size_t)(k0 + r) * 3072 + dc];
            const float* vs = &qkv[base + 2048 + (size_t)(k0 + r) * 3072 + dc];
#pragma unroll
            for (int i = 0; i < 16; i += 4) {
                float4 kv = *(const float4*)&ks[i];
                float kx[4] = {kv.x, kv.y, kv.z, kv.w};
#pragma unroll
                for (int u = 0; u < 4; u++) {
                    float hh = f2tf32(kx[u]);
                    Kth[(dc + i + u) * AST + r] = hh;
                    Ktl[(dc + i + u) * AST + r] = f2tf32(kx[u] - hh);
                }
                float4 vv = *(const float4*)&vs[i];
                float v0 = f2tf32(vv.x), v1 = f2tf32(vv.y), v2 = f2tf32(vv.z), v3 = f2tf32(vv.w);
                *(float4*)&Vh[r * AST + dc + i] = make_float4(v0, v1, v2, v3);
                *(float4*)&Vl[r * AST + dc + i] =
                    make_float4(f2tf32(vv.x - v0), f2tf32(vv.y - v1),
                                f2tf32(vv.z - v2), f2tf32(vv.w - v3));
            }
        }
        __syncthreads();

        // S = Q @ K^T (3xTF32)
        float s[8][4];
#pragma unroll
        for (int nt = 0; nt < 8; nt++)
#pragma unroll
            for (int cc = 0; cc < 4; cc++) s[nt][cc] = 0.f;
#pragma unroll
        for (int ksl = 0; ksl < 8; ksl++) {
            int kk = ksl * 8;
            const float* ap = &Qh[row_lo * AST + kk + tig];
            const float* al = &Ql[row_lo * AST + kk + tig];
            unsigned afh[4] = {__float_as_uint(ap[0]), __float_as_uint(ap[8 * AST]),
                               __float_as_uint(ap[4]), __float_as_uint(ap[8 * AST + 4])};
            unsigned afl[4] = {__float_as_uint(al[0]), __float_as_uint(al[8 * AST]),
                               __float_as_uint(al[4]), __float_as_uint(al[8 * AST + 4])};
#pragma unroll
            for (int nt = 0; nt < 8; nt++) {
                const float* bp = &Kth[(kk + tig) * AST + nt * 8 + gid];
                const float* bl = &Ktl[(kk + tig) * AST + nt * 8 + gid];
                unsigned bfh[2] = {__float_as_uint(bp[0]), __float_as_uint(bp[4 * AST])};
                unsigned bfl[2] = {__float_as_uint(bl[0]), __float_as_uint(bl[4 * AST])};
                mma_tf32(s[nt][0], s[nt][1], s[nt][2], s[nt][3],
                         afh[0], afh[1], afh[2], afh[3], bfl[0], bfl[1]);
                mma_tf32(s[nt][0], s[nt][1], s[nt][2], s[nt][3],
                         afl[0], afl[1], afl[2], afl[3], bfh[0], bfh[1]);
                mma_tf32(s[nt][0], s[nt][1], s[nt][2], s[nt][3],
                         afh[0], afh[1], afh[2], afh[3], bfh[0], bfh[1]);
            }
        }
        // mask + scale
        bool need_mask = (kt >= 2 * qb);
#pragma unroll
        for (int nt = 0; nt < 8; nt++) {
#pragma unroll
            for (int cc = 0; cc < 4; cc++) {
                int row = q0 + row_lo + ((cc >> 1) << 3);
                int col = k0 + nt * 8 + 2 * tig + (cc & 1);
                if (need_mask && col > row) s[nt][cc] = -1e30f;
                else s[nt][cc] *= 0.125f;
            }
        }
        // online softmax (warp-local: quad shuffles)
        float mx0 = -1e30f, mx1 = -1e30f;
#pragma unroll
        for (int nt = 0; nt < 8; nt++) {
            mx0 = fmaxf(mx0, fmaxf(s[nt][0], s[nt][1]));
            mx1 = fmaxf(mx1, fmaxf(s[nt][2], s[nt][3]));
        }
        mx0 = fmaxf(mx0, __shfl_xor_sync(0xffffffffu, mx0, 1));
        mx0 = fmaxf(mx0, __shfl_xor_sync(0xffffffffu, mx0, 2));
        mx1 = fmaxf(mx1, __shfl_xor_sync(0xffffffffu, mx1, 1));
        mx1 = fmaxf(mx1, __shfl_xor_sync(0xffffffffu, mx1, 2));
        float mn0 = fmaxf(m0, mx0), mn1 = fmaxf(m1, mx1);
        float a0 = __expf(m0 - mn0), a1 = __expf(m1 - mn1);
        m0 = mn0; m1 = mn1;
        float rs0 = 0.f, rs1 = 0.f;
#pragma unroll
        for (int nt = 0; nt < 8; nt++) {
            s[nt][0] = __expf(s[nt][0] - mn0); rs0 += s[nt][0];
            s[nt][1] = __expf(s[nt][1] - mn0); rs0 += s[nt][1];
            s[nt][2] = __expf(s[nt][2] - mn1); rs1 += s[nt][2];
            s[nt][3] = __expf(s[nt][3] - mn1); rs1 += s[nt][3];
        }
        rs0 += __shfl_xor_sync(0xffffffffu, rs0, 1);
        rs0 += __shfl_xor_sync(0xffffffffu, rs0, 2);
        rs1 += __shfl_xor_sync(0xffffffffu, rs1, 1);
        rs1 += __shfl_xor_sync(0xffffffffu, rs1, 2);
        l0 = l0 * a0 + rs0; l1 = l1 * a1 + rs1;
#pragma unroll
        for (int nt = 0; nt < 8; nt++) {
            acc[nt][0] *= a0; acc[nt][1] *= a0;
            acc[nt][2] *= a1; acc[nt][3] *= a1;
        }
        // store P split (own-warp rows only)
#pragma unroll
        for (int nt = 0; nt < 8; nt++) {
            int col = nt * 8 + 2 * tig;
            float p0 = f2tf32(s[nt][0]), p1 = f2tf32(s[nt][1]);
            *(float2*)&Ph[row_lo * AST + col] = make_float2(p0, p1);
            *(float2*)&Pl[row_lo * AST + col] =
                make_float2(f2tf32(s[nt][0] - p0), f2tf32(s[nt][1] - p1));
            float p2 = f2tf32(s[nt][2]), p3 = f2tf32(s[nt][3]);
            *(float2*)&Ph[(row_lo + 8) * AST + col] = make_float2(p2, p3);
            *(float2*)&Pl[(row_lo + 8) * AST + col] =
                make_float2(f2tf32(s[nt][2] - p2), f2tf32(s[nt][3] - p3));
        }
        __syncwarp();
        // acc += P @ V (3xTF32, contraction over 64 keys)
#pragma unroll
        for (int ksl = 0; ksl < 8; ksl++) {
            int kk = ksl * 8;
            const float* ap = &Ph[row_lo * AST + kk + tig];
            const float* al = &Pl[row_lo * AST + kk + tig];
            unsigned afh[4] = {__float_as_uint(ap[0]), __float_as_uint(ap[8 * AST]),
                               __float_as_uint(ap[4]), __float_as_uint(ap[8 * AST + 4])};
            unsigned afl[4] = {__float_as_uint(al[0]), __float_as_uint(al[8 * AST]),
                               __float_as_uint(al[4]), __float_as_uint(al[8 * AST + 4])};
#pragma unroll
            for (int nt = 0; nt < 8; nt++) {
                const float* bp = &Vh[(kk + tig) * AST + nt * 8 + gid];
                const float* bl = &Vl[(kk + tig) * AST + nt * 8 + gid];
                unsigned bfh[2] = {__float_as_uint(bp[0]), __float_as_uint(bp[4 * AST])};
                unsigned bfl[2] = {__float_as_uint(bl[0]), __float_as_uint(bl[4 * AST])};
                mma_tf32(acc[nt][0], acc[nt][1], acc[nt][2], acc[nt][3],
                         afh[0], afh[1], afh[2], afh[3], bfl[0], bfl[1]);
                mma_tf32(acc[nt][0], acc[nt][1], acc[nt][2], acc[nt][3],
                         afl[0], afl[1], afl[2], afl[3], bfh[0], bfh[1]);
                mma_tf32(acc[nt][0], acc[nt][1], acc[nt][2], acc[nt][3],
                         afh[0], afh[1], afh[2], afh[3], bfh[0], bfh[1]);
            }
        }
        __syncthreads();
    }
    // epilogue
    float inv0 = 1.f / l0, inv1 = 1.f / l1;
    size_t obase = (size_t)(b * Lseq) * Dm + h * 64;
    int grow = q0 + row_lo;
#pragma unroll
    for (int nt = 0; nt < 8; nt++) {
        int col = nt * 8 + 2 * tig;
        *(float2*)&out[obase + (size_t)grow * Dm + col] =
            make_float2(acc[nt][0] * inv0, acc[nt][1] * inv0);
        *(float2*)&out[obase + (size_t)(grow + 8) * Dm + col] =
            make_float2(acc[nt][2] * inv1, acc[nt][3] * inv1);
    }
}

// ---------------- small SGEMM (for Wbeta, N=16) ----------------
__global__ void gemm128(const float* __restrict__ A, const float* __restrict__ Bm,
                        float* __restrict__ C, int M, int N, int K) {
    __shared__ float As[16][128];
    __shared__ float Bs[16][64];
    int tid = threadIdx.x;
    int tx = tid & 15, ty = tid >> 4;
    int m0 = blockIdx.y * 128, n0 = blockIdx.x * 64;
    int arow = tid >> 2, ak4 = (tid & 3) * 4, brow = tid >> 4, bc4 = (tid & 15) * 4;
    float acc[8][4];
#pragma unroll
    for (int i = 0; i < 8; i++)
#pragma unroll
        for (int j = 0; j < 4; j++) acc[i][j] = 0.f;
    for (int kk = 0; kk < K; kk += 16) {
#pragma unroll
        for (int half = 0; half < 2; half++) {
            int r = arow + half * 64;
            float4 a4 = *(const float4*)&A[(size_t)(m0 + r) * K + kk + ak4];
            As[ak4+0][r] = a4.x; As[ak4+1][r] = a4.y; As[ak4+2][r] = a4.z; As[ak4+3][r] = a4.w;
        }
        if (n0 + bc4 < N)
            *(float4*)&Bs[brow][bc4] = *(const float4*)&Bm[(size_t)(kk + brow) * N + n0 + bc4];
        else
            *(float4*)&Bs[brow][bc4] = make_float4(0.f, 0.f, 0.f, 0.f);
        __syncthreads();
#pragma unroll
        for (int k2 = 0; k2 < 16; k2++) {
            float4 b4 = *(float4*)&Bs[k2][tx * 4];
            float4 aa = *(float4*)&As[k2][ty * 8];
            float4 ab = *(float4*)&As[k2][ty * 8 + 4];
            float av[8] = {aa.x, aa.y, aa.z, aa.w, ab.x, ab.y, ab.z, ab.w};
            float bv[4] = {b4.x, b4.y, b4.z, b4.w};
#pragma unroll
            for (int i = 0; i < 8; i++)
#pragma unroll
                for (int j = 0; j < 4; j++) acc[i][j] += av[i] * bv[j];
        }
        __syncthreads();
    }
    if (n0 + tx * 4 < N)
#pragma unroll
        for (int i = 0; i < 8; i++)
            *(float4*)&C[(size_t)(m0 + ty * 8 + i) * N + n0 + tx * 4] =
                make_float4(acc[i][0], acc[i][1], acc[i][2], acc[i][3]);
}

// ---------------- conv + k-normalize ----------------
__global__ void conv_kernel(const float* __restrict__ dqr, const float* __restrict__ dkr,
                            const float* __restrict__ cqw, const float* __restrict__ cqb,
                            const float* __restrict__ ckw, const float* __restrict__ ckb,
                            float* __restrict__ dq, float* __restrict__ dk) {
    int bt = blockIdx.x, t = bt & (Lseq - 1), tid = threadIdx.x, c0 = tid * 4;
    float xq[4][4], xk[4][4];
#pragma unroll
    for (int j = 0; j < 4; j++) {
        if (t - 3 + j >= 0) {
            float4 a = *(const float4*)&dqr[(size_t)(bt - 3 + j) * Dm + c0];
            xq[j][0] = a.x; xq[j][1] = a.y; xq[j][2] = a.z; xq[j][3] = a.w;
            float4 b = *(const float4*)&dkr[(size_t)(bt - 3 + j) * Dm + c0];
            xk[j][0] = b.x; xk[j][1] = b.y; xk[j][2] = b.z; xk[j][3] = b.w;
        } else {
#pragma unroll
            for (int u = 0; u < 4; u++) { xq[j][u] = 0.f; xk[j][u] = 0.f; }
        }
    }
    float4 qb4 = *(const float4*)&cqb[c0];
    float4 kb4 = *(const float4*)&ckb[c0];
    float qbv[4] = {qb4.x, qb4.y, qb4.z, qb4.w}, kbv[4] = {kb4.x, kb4.y, kb4.z, kb4.w};
    float oq[4], ok[4];
#pragma unroll
    for (int u = 0; u < 4; u++) {
        float4 wq = *(const float4*)&cqw[(c0 + u) * 4];
        float4 wk = *(const float4*)&ckw[(c0 + u) * 4];
        oq[u] = qbv[u] + wq.x*xq[0][u] + wq.y*xq[1][u] + wq.z*xq[2][u] + wq.w*xq[3][u];
        ok[u] = kbv[u] + wk.x*xk[0][u] + wk.y*xk[1][u] + wk.z*xk[2][u] + wk.w*xk[3][u];
    }
    *(float4*)&dq[(size_t)bt * Dm + c0] = make_float4(oq[0], oq[1], oq[2], oq[3]);
    float ss = ok[0]*ok[0] + ok[1]*ok[1] + ok[2]*ok[2] + ok[3]*ok[3];
    ss += __shfl_xor_sync(0xffffffffu, ss, 1, 16);
    ss += __shfl_xor_sync(0xffffffffu, ss, 2, 16);
    ss += __shfl_xor_sync(0xffffffffu, ss, 4, 16);
    ss += __shfl_xor_sync(0xffffffffu, ss, 8, 16);
    float rn = 1.f / fmaxf(sqrtf(ss), 1e-12f);
    *(float4*)&dk[(size_t)bt * Dm + c0] = make_float4(ok[0]*rn, ok[1]*rn, ok[2]*rn, ok[3]*rn);
}

// ---------------- sequential delta scan ----------------
__global__ void scan_kernel(const float* __restrict__ dq, const float* __restrict__ dk,
                            const float* __restrict__ dv, const float* __restrict__ beta_pre,
                            const float* __restrict__ bbeta,
                            float* __restrict__ ys, float* __restrict__ outS,
                            float* __restrict__ outZ) {
    int bh = blockIdx.x, b = bh >> 4, h = bh & 15;
    int tid = threadIdx.x;
    int r = tid >> 2, qq = tid & 3, c0 = qq * 16;
    int lane = tid & 63, g = tid >> 6;
    __shared__ float qs[64], ks[64], vs[64], zs[64];
    __shared__ float red[8];
    __shared__ float sbeta;
    float S[16];
#pragma unroll
    for (int j = 0; j < 16; j++) S[j] = 0.f;
    if (tid < 64) zs[tid] = 0.f;
    size_t rowbase = (size_t)(b * Lseq) * Dm + (size_t)h * 64;
    size_t betabase = (size_t)(b * Lseq) * Hh + h;
    float pre = 0.f;
    if (g == 0) pre = dq[rowbase + lane];
    else if (g == 1) pre = dk[rowbase + lane];
    else if (g == 2) pre = dv[rowbase + lane];
    else if (lane == 0) pre = beta_pre[betabase] + bbeta[h];
    for (int t = 0; t < Lseq; t++) {
        if (g == 0) qs[lane] = pre;
        else if (g == 1) ks[lane] = pre;
        else if (g == 2) vs[lane] = pre;
        else if (lane == 0) sbeta = 1.f / (1.f + __expf(-pre));
        __syncthreads();
        if (t + 1 < Lseq) {
            size_t row = rowbase + (size_t)(t + 1) * Dm;
            if (g == 0) pre = dq[row + lane];
            else if (g == 1) pre = dk[row + lane];
            else if (g == 2) pre = dv[row + lane];
            else if (lane == 0) pre = beta_pre[betabase + (size_t)(t + 1) * Hh] + bbeta[h];
        }
        float accy = 0.f, acco = 0.f;
#pragma unroll
        for (int j = 0; j < 16; j += 4) {
            float4 q4 = *(float4*)&qs[c0 + j];
            float4 k4 = *(float4*)&ks[c0 + j];
            accy += S[j]*q4.x + S[j+1]*q4.y + S[j+2]*q4.z + S[j+3]*q4.w;
            acco += S[j]*k4.x + S[j+1]*k4.y + S[j+2]*k4.z + S[j+3]*k4.w;
        }
        accy += __shfl_xor_sync(0xffffffffu, accy, 1);
        accy += __shfl_xor_sync(0xffffffffu, accy, 2);
        acco += __shfl_xor_sync(0xffffffffu, acco, 1);
        acco += __shfl_xor_sync(0xffffffffu, acco, 2);
        float dp = (tid < 64) ? zs[tid] * qs[tid] : 0.f;
#pragma unroll
        for (int off = 16; off >= 1; off >>= 1) dp += __shfl_xor_sync(0xffffffffu, dp, off);
        if ((tid & 31) == 0) red[tid >> 5] = dp;
        __syncthreads();
        float denom = red[0] + red[1] + 1e-6f;
        float bet = sbeta;
        float delta = vs[r] - acco;
        if (qq == 0) ys[rowbase + (size_t)t * Dm + r] = accy / denom;
        float bd = bet * delta;
#pragma unroll
        for (int j = 0; j < 16; j += 4) {
            float4 k4 = *(float4*)&ks[c0 + j];
            S[j] += bd*k4.x; S[j+1] += bd*k4.y; S[j+2] += bd*k4.z; S[j+3] += bd*k4.w;
        }
        if (tid < 64) zs[tid] += bet * ks[tid];
        __syncthreads();
    }
    size_t sb2 = (size_t)bh * 4096;
#pragma unroll
    for (int j = 0; j < 16; j++) outS[sb2 + (size_t)r * 64 + c0 + j] = S[j];
    if (tid < 64) outZ[(size_t)bh * 64 + tid] = zs[tid];
}

// ---------------- layernorm ----------------
__global__ void ln_kernel(float* __restrict__ x, const float* __restrict__ gw,
                          const float* __restrict__ bw) {
    __shared__ float rs[8], rq[8];
    int row = blockIdx.x, tid = threadIdx.x;
    float* xr = x + (size_t)row * Dm;
    float4 v = *(float4*)&xr[tid * 4];
    float s = v.x + v.y + v.z + v.w;
    float s2 = v.x*v.x + v.y*v.y + v.z*v.z + v.w*v.w;
#pragma unroll
    for (int off = 16; off >= 1; off >>= 1) {
        s  += __shfl_xor_sync(0xffffffffu, s, off);
        s2 += __shfl_xor_sync(0xffffffffu, s2, off);
    }
    if ((tid & 31) == 0) { rs[tid >> 5] = s; rq[tid >> 5] = s2; }
    __syncthreads();
    float tot = 0.f, tot2 = 0.f;
#pragma unroll
    for (int w = 0; w < 8; w++) { tot += rs[w]; tot2 += rq[w]; }
    float mean = tot * (1.f / 1024.f);
    float var = tot2 * (1.f / 1024.f) - mean * mean;
    float rstd = rsqrtf(var + 1e-5f);
    float4 g4 = *(const float4*)&gw[tid * 4];
    float4 b4 = *(const float4*)&bw[tid * 4];
    v.x = (v.x - mean) * rstd * g4.x + b4.x;
    v.y = (v.y - mean) * rstd * g4.y + b4.y;
    v.z = (v.z - mean) * rstd * g4.z + b4.z;
    v.w = (v.w - mean) * rstd * g4.w + b4.w;
    *(float4*)&xr[tid * 4] = v;
}

// ---------------- gate fusion ----------------
__global__ void gate_kernel(const float* __restrict__ gp, const float* __restrict__ bg,
                            const float* __restrict__ fl, const float* __restrict__ dl,
                            float* __restrict__ out) {
    int row = blockIdx.x, tid = threadIdx.x;
    size_t i = (size_t)row * Dm + tid * 4;
    float4 gpv = *(const float4*)&gp[i];
    float4 bgv = *(const float4*)&bg[tid * 4];
    float4 flv = *(const float4*)&fl[i];
    float4 dlv = *(const float4*)&dl[i];
    float4 o;
    float g0 = 1.f/(1.f+__expf(-(gpv.x+bgv.x))); o.x = g0*flv.x + (1.f-g0)*dlv.x;
    float g1 = 1.f/(1.f+__expf(-(gpv.y+bgv.y))); o.y = g1*flv.y + (1.f-g1)*dlv.y;
    float g2 = 1.f/(1.f+__expf(-(gpv.z+bgv.z))); o.z = g2*flv.z + (1.f-g2)*dlv.z;
    float g3 = 1.f/(1.f+__expf(-(gpv.w+bgv.w))); o.w = g3*flv.w + (1.f-g3)*dlv.w;
    *(float4*)&out[i] = o;
}

// ---------------- launcher ----------------
extern "C" void kernel_launch(void* const* d_in, const int* in_sizes, int n_in,
                              void* d_out, int out_size) {
    const float* x     = (const float*)d_in[0];
    const float* Wqkv  = (const float*)d_in[1];
    const float* Wout  = (const float*)d_in[2];
    const float* Wgate = (const float*)d_in[3];
    const float* bgate = (const float*)d_in[4];
    const float* fn_g  = (const float*)d_in[5];
    const float* fn_b  = (const float*)d_in[6];
    const float* dn_g  = (const float*)d_in[7];
    const float* dn_b  = (const float*)d_in[8];
    const float* dWq   = (const float*)d_in[9];
    const float* dWk   = (const float*)d_in[10];
    const float* dWv   = (const float*)d_in[11];
    const float* dWo   = (const float*)d_in[12];
    const float* Wbeta = (const float*)d_in[13];
    const float* bbeta = (const float*)d_in[14];
    const float* cq_w  = (const float*)d_in[15];
    const float* cq_b  = (const float*)d_in[16];
    const float* ck_w  = (const float*)d_in[17];
    const float* ck_b  = (const float*)d_in[18];
    const float* ln_g  = (const float*)d_in[19];
    const float* ln_b  = (const float*)d_in[20];
    float* out = (float*)d_out;

    float *p_qkv, *p_attn, *p_flash, *p_dqr, *p_dkr, *p_dq, *p_dk, *p_dv;
    float *p_beta, *p_ys, *p_delta, *p_gate;
    cudaGetSymbolAddress((void**)&p_qkv,  g_qkv);
    cudaGetSymbolAddress((void**)&p_attn, g_attn);
    cudaGetSymbolAddress((void**)&p_flash,g_flash);
    cudaGetSymbolAddress((void**)&p_dqr,  g_dqr);
    cudaGetSymbolAddress((void**)&p_dkr,  g_dkr);
    cudaGetSymbolAddress((void**)&p_dq,   g_dq);
    cudaGetSymbolAddress((void**)&p_dk,   g_dk);
    cudaGetSymbolAddress((void**)&p_dv,   g_dv);
    cudaGetSymbolAddress((void**)&p_beta, g_beta);
    cudaGetSymbolAddress((void**)&p_ys,   g_ys);
    cudaGetSymbolAddress((void**)&p_delta,g_delta);
    cudaGetSymbolAddress((void**)&p_gate, g_gate);

    float* pS = (out_size >= 4327424) ? out + 4194304 : p_qkv;
    float* pZ = (out_size >= 4327424) ? out + 4325376 : p_qkv + 4096;

    cudaFuncSetAttribute(gemm_tf32_t<false>, cudaFuncAttributeMaxDynamicSharedMemorySize, GEMM_SMEM_FAST);
    cudaFuncSetAttribute(gemm_tf32_t<true>,  cudaFuncAttributeMaxDynamicSharedMemorySize, GEMM_SMEM_P3);
    cudaFuncSetAttribute(attn_mma, cudaFuncAttributeMaxDynamicSharedMemorySize, ATTN_SMEM);

    // projections
    gemm_tf32_t<false><<<dim3(24, 32), 256, GEMM_SMEM_FAST>>>(x, Wqkv,  p_qkv,  BL, 3 * Dm, Dm);
    gemm_tf32_t<true><<<dim3(8, 32), 256, GEMM_SMEM_P3>>>(x, dWq,   p_dqr,  BL, Dm, Dm);
    gemm_tf32_t<true><<<dim3(8, 32), 256, GEMM_SMEM_P3>>>(x, dWk,   p_dkr,  BL, Dm, Dm);
    gemm_tf32_t<true><<<dim3(8, 32), 256, GEMM_SMEM_P3>>>(x, dWv,   p_dv,   BL, Dm, Dm);
    gemm_tf32_t<false><<<dim3(8, 32), 256, GEMM_SMEM_FAST>>>(x, Wgate, p_gate, BL, Dm, Dm);
    gemm128<<<dim3(1, 32), 256>>>(x, Wbeta, p_beta, BL, Hh, Dm);

    // conv + k-normalize
    conv_kernel<<<BL, 256>>>(p_dqr, p_dkr, cq_w, cq_b, ck_w, ck_b, p_dq, p_dk);

    // flash attention (mma)
    attn_mma<<<dim3(16, 32), 256, ATTN_SMEM>>>(p_qkv, p_attn);
    gemm_tf32_t<false><<<dim3(8, 32), 256, GEMM_SMEM_FAST>>>(p_attn, Wout, p_flash, BL, Dm, Dm);
    ln_kernel<<<BL, 256>>>(p_flash, fn_g, fn_b);

    // delta scan
    scan_kernel<<<32, 256>>>(p_dq, p_dk, p_dv, p_beta, bbeta, p_ys, pS, pZ);
    gemm_tf32_t<false><<<dim3(8, 32), 256, GEMM_SMEM_FAST>>>(p_ys, dWo, p_delta, BL, Dm, Dm);
    ln_kernel<<<BL, 256>>>(p_delta, ln_g, ln_b);
    ln_kernel<<<BL, 256>>>(p_delta, dn_g, dn_b);

    // gate
    gate_kernel<<<BL, 256>>>(p_gate, bgate, p_flash, p_delta, out);
}

// round 8
// speedup vs baseline: 1.9736x; 1.2253x over previous
#include <cuda_runtime.h>
#include <math.h>
#include <stdint.h>

#define Bsz 2
#define Lseq 2048
#define Dm 1024
#define Hh 16
#define BL (Bsz*Lseq)   // 4096

// ---------------- scratch ----------------
__device__ float g_qkv[BL*3*Dm];
__device__ float g_attn[BL*Dm];
__device__ float g_flash[BL*Dm];
__device__ float g_dqr[BL*Dm];
__device__ float g_dkr[BL*Dm];
__device__ float g_dq[BL*Dm];
__device__ float g_dk[BL*Dm];
__device__ float g_dv[BL*Dm];
__device__ float g_beta[BL*Hh];
__device__ float g_ys[BL*Dm];
__device__ float g_delta[BL*Dm];
__device__ float g_gate[BL*Dm];

// ---------------- tf32 helpers ----------------
__device__ __forceinline__ float f2tf32(float x) {
    float r;
    asm("cvt.rna.tf32.f32 %0, %1;" : "=f"(r) : "f"(x));
    return r;
}
__device__ __forceinline__ void mma_tf32(float& c0, float& c1, float& c2, float& c3,
                                         unsigned a0, unsigned a1, unsigned a2, unsigned a3,
                                         unsigned b0, unsigned b1) {
    asm volatile("mma.sync.aligned.m16n8k8.row.col.f32.tf32.tf32.f32 "
                 "{%0,%1,%2,%3}, {%4,%5,%6,%7}, {%8,%9}, {%0,%1,%2,%3};"
                 : "+f"(c0), "+f"(c1), "+f"(c2), "+f"(c3)
                 : "r"(a0), "r"(a1), "r"(a2), "r"(a3), "r"(b0), "r"(b1));
}

// ---------------- tf32 tensor-core GEMM (optionally 3xTF32 precise) ----------------
#define AS_STRIDE 36
#define BS_STRIDE 132
#define ABUF (128*AS_STRIDE)
#define BBUF (32*BS_STRIDE)
#define GEMM_SMEM_FAST ((2*ABUF + 2*BBUF) * 4)
#define GEMM_SMEM_P3   ((4*ABUF + 4*BBUF) * 4)

template<bool P3>
__device__ __forceinline__ void stage_tile(float* Ah, float* Al, float* Bh, float* Bl,
                                           const float4* ra, const float4* rb, int tid) {
#pragma unroll
    for (int i = 0; i < 4; i++) {
        int e = tid + i * 256;
        int ar = e >> 3, ac = (e & 7) * 4;
        float* ap = &Ah[ar * AS_STRIDE + ac];
        float4 v = ra[i];
        float h0 = f2tf32(v.x), h1 = f2tf32(v.y), h2 = f2tf32(v.z), h3 = f2tf32(v.w);
        ap[0] = h0; ap[1] = h1; ap[2] = h2; ap[3] = h3;
        if (P3) {
            float* al = &Al[ar * AS_STRIDE + ac];
            al[0] = f2tf32(v.x - h0); al[1] = f2tf32(v.y - h1);
            al[2] = f2tf32(v.z - h2); al[3] = f2tf32(v.w - h3);
        }
        int br = e >> 5, bc = (e & 31) * 4;
        float4 w = rb[i];
        float g0 = f2tf32(w.x), g1 = f2tf32(w.y), g2 = f2tf32(w.z), g3 = f2tf32(w.w);
        *(float4*)&Bh[br * BS_STRIDE + bc] = make_float4(g0, g1, g2, g3);
        if (P3) {
            *(float4*)&Bl[br * BS_STRIDE + bc] =
                make_float4(f2tf32(w.x - g0), f2tf32(w.y - g1),
                            f2tf32(w.z - g2), f2tf32(w.w - g3));
        }
    }
}

template<bool P3>
__global__ void gemm_tf32_t(const float* __restrict__ A, const float* __restrict__ B,
                            float* __restrict__ C, int M, int N, int K) {
    extern __shared__ float sm[];
    float* Ah = sm;
    float* Bh = sm + 2 * ABUF;
    float* Al = P3 ? sm + 2 * ABUF + 2 * BBUF : sm;
    float* Bl = P3 ? Al + 2 * ABUF : sm;

    int tid = threadIdx.x;
    int warp = tid >> 5, lane = tid & 31;
    int gid = lane >> 2, tig = lane & 3;
    int warp_m = (warp >> 2) * 64;
    int warp_n = (warp & 3) * 32;
    int m0 = blockIdx.y * 128, n0 = blockIdx.x * 128;

    float acc[4][4][4];
#pragma unroll
    for (int i = 0; i < 4; i++)
#pragma unroll
        for (int j = 0; j < 4; j++)
#pragma unroll
            for (int u = 0; u < 4; u++) acc[i][j][u] = 0.f;

    float4 ra[4], rb[4];
    int kt_total = K >> 5;

#pragma unroll
    for (int i = 0; i < 4; i++) {
        int e = tid + i * 256;
        int ar = e >> 3, ac = (e & 7) * 4;
        ra[i] = *(const float4*)&A[(size_t)(m0 + ar) * K + ac];
        int br = e >> 5, bc = (e & 31) * 4;
        rb[i] = *(const float4*)&B[(size_t)br * N + n0 + bc];
    }
    stage_tile<P3>(Ah, Al, Bh, Bl, ra, rb, tid);
    __syncthreads();

    for (int t = 0; t < kt_total; t++) {
        int cur = t & 1;
        float* Ahc = Ah + cur * ABUF;
        float* Bhc = Bh + cur * BBUF;
        float* Alc = Al + cur * ABUF;
        float* Blc = Bl + cur * BBUF;

        if (t + 1 < kt_total) {
            int kk = (t + 1) << 5;
#pragma unroll
            for (int i = 0; i < 4; i++) {
                int e = tid + i * 256;
                int ar = e >> 3, ac = (e & 7) * 4;
                ra[i] = *(const float4*)&A[(size_t)(m0 + ar) * K + kk + ac];
                int br = e >> 5, bc = (e & 31) * 4;
                rb[i] = *(const float4*)&B[(size_t)(kk + br) * N + n0 + bc];
            }
        }

#pragma unroll
        for (int ks = 0; ks < 4; ks++) {
            int k0 = ks * 8;
            unsigned afh[4][4], bfh[4][2];
            unsigned afl[4][4], bfl[4][2];
#pragma unroll
            for (int mt = 0; mt < 4; mt++) {
                int r = warp_m + mt * 16 + gid;
                const float* ap = &Ahc[r * AS_STRIDE + k0 + tig];
                afh[mt][0] = __float_as_uint(ap[0]);
                afh[mt][1] = __float_as_uint(ap[AS_STRIDE * 8]);
                afh[mt][2] = __float_as_uint(ap[4]);
                afh[mt][3] = __float_as_uint(ap[AS_STRIDE * 8 + 4]);
                if (P3) {
                    const float* al = &Alc[r * AS_STRIDE + k0 + tig];
                    afl[mt][0] = __float_as_uint(al[0]);
                    afl[mt][1] = __float_as_uint(al[AS_STRIDE * 8]);
                    afl[mt][2] = __float_as_uint(al[4]);
                    afl[mt][3] = __float_as_uint(al[AS_STRIDE * 8 + 4]);
                }
            }
#pragma unroll
            for (int nt = 0; nt < 4; nt++) {
                int c = warp_n + nt * 8 + gid;
                const float* bp = &Bhc[(k0 + tig) * BS_STRIDE + c];
                bfh[nt][0] = __float_as_uint(bp[0]);
                bfh[nt][1] = __float_as_uint(bp[BS_STRIDE * 4]);
                if (P3) {
                    const float* bl = &Blc[(k0 + tig) * BS_STRIDE + c];
                    bfl[nt][0] = __float_as_uint(bl[0]);
                    bfl[nt][1] = __float_as_uint(bl[BS_STRIDE * 4]);
                }
            }
#pragma unroll
            for (int mt = 0; mt < 4; mt++)
#pragma unroll
                for (int nt = 0; nt < 4; nt++) {
                    if (P3) {
                        mma_tf32(acc[mt][nt][0], acc[mt][nt][1], acc[mt][nt][2], acc[mt][nt][3],
                                 afh[mt][0], afh[mt][1], afh[mt][2], afh[mt][3],
                                 bfl[nt][0], bfl[nt][1]);
                        mma_tf32(acc[mt][nt][0], acc[mt][nt][1], acc[mt][nt][2], acc[mt][nt][3],
                                 afl[mt][0], afl[mt][1], afl[mt][2], afl[mt][3],
                                 bfh[nt][0], bfh[nt][1]);
                    }
                    mma_tf32(acc[mt][nt][0], acc[mt][nt][1], acc[mt][nt][2], acc[mt][nt][3],
                             afh[mt][0], afh[mt][1], afh[mt][2], afh[mt][3],
                             bfh[nt][0], bfh[nt][1]);
                }
        }

        if (t + 1 < kt_total) {
            int nxt = (t + 1) & 1;
            stage_tile<P3>(Ah + nxt * ABUF, Al + nxt * ABUF,
                           Bh + nxt * BBUF, Bl + nxt * BBUF, ra, rb, tid);
        }
        __syncthreads();
    }

#pragma unroll
    for (int mt = 0; mt < 4; mt++) {
#pragma unroll
        for (int nt = 0; nt < 4; nt++) {
            int row = m0 + warp_m + mt * 16 + gid;
            int col = n0 + warp_n + nt * 8 + 2 * tig;
            *(float2*)&C[(size_t)row * N + col] =
                make_float2(acc[mt][nt][0], acc[mt][nt][1]);
            *(float2*)&C[(size_t)(row + 8) * N + col] =
                make_float2(acc[mt][nt][2], acc[mt][nt][3]);
        }
    }
}

// ---------------- mma-based causal flash attention (single-pass tf32) ----------------
// Q-block 128 rows/CTA, K-tiles 64. Staging is pure float4 copies (mma truncates
// fp32->tf32 in HW). K kept natural [key][d]; B-fragment read directly (conflict-free).
#define AST 68
#define ATTN_SMEM (384 * AST * 4)   // Q(128)+K(64)+V(64)+P(128) rows = 104448 B

__global__ void __launch_bounds__(256, 2) attn_mma(const float* __restrict__ qkv,
                                                   float* __restrict__ out) {
    extern __shared__ float sm[];
    float* Qs = sm;               // [128][AST] (row, d)
    float* Ks = sm + 128 * AST;   // [64][AST]  (key, d)
    float* Vs = sm + 192 * AST;   // [64][AST]  (key, d)
    float* Ps = sm + 256 * AST;   // [128][AST] (row, key)

    int qb = (int)gridDim.x - 1 - (int)blockIdx.x;  // heavy tiles first
    int bh = blockIdx.y;
    int b = bh >> 4, h = bh & 15;
    int tid = threadIdx.x, warp = tid >> 5, lane = tid & 31;
    int gid = lane >> 2, tig = lane & 3;
    size_t base = (size_t)(b * Lseq) * 3072 + h * 64;
    int q0 = qb * 128;
    int row_lo = warp * 16 + gid;

    // stage Q (raw copy)
    {
        int r = tid >> 1, dc = (tid & 1) * 32;
        const float4* src = (const float4*)&qkv[base + (size_t)(q0 + r) * 3072 + dc];
        float4* dst = (float4*)&Qs[r * AST + dc];
#pragma unroll
        for (int i = 0; i < 8; i++) dst[i] = src[i];
    }
    float acc[8][4];
#pragma unroll
    for (int nt = 0; nt < 8; nt++)
#pragma unroll
        for (int cc = 0; cc < 4; cc++) acc[nt][cc] = 0.f;
    float m0 = -1e30f, m1 = -1e30f, l0 = 0.f, l1 = 0.f;
    __syncthreads();

    int ktend = 2 * qb + 1;
    for (int kt = 0; kt <= ktend; kt++) {
        int k0 = kt * 64;
        {
            int r = tid >> 2, dc = (tid & 3) * 16;
            const float4* ksrc = (const float4*)&qkv[base + 1024 + (size_t)(k0 + r) * 3072 + dc];
            const float4* vsrc = (const float4*)&qkv[base + 2048 + (size_t)(k0 + r) * 3072 + dc];
            float4* kdst = (float4*)&Ks[r * AST + dc];
            float4* vdst = (float4*)&Vs[r * AST + dc];
#pragma unroll
            for (int i = 0; i < 4; i++) { kdst[i] = ksrc[i]; vdst[i] = vsrc[i]; }
        }
        __syncthreads();

        // S = Q @ K^T
        float s[8][4];
#pragma unroll
        for (int nt = 0; nt < 8; nt++)
#pragma unroll
            for (int cc = 0; cc < 4; cc++) s[nt][cc] = 0.f;
#pragma unroll
        for (int ksl = 0; ksl < 8; ksl++) {
            int kk = ksl * 8;
            const float* ap = &Qs[row_lo * AST + kk + tig];
            unsigned af0 = __float_as_uint(ap[0]);
            unsigned af1 = __float_as_uint(ap[8 * AST]);
            unsigned af2 = __float_as_uint(ap[4]);
            unsigned af3 = __float_as_uint(ap[8 * AST + 4]);
#pragma unroll
            for (int nt = 0; nt < 8; nt++) {
                const float* bp = &Ks[(nt * 8 + gid) * AST + kk + tig];
                mma_tf32(s[nt][0], s[nt][1], s[nt][2], s[nt][3],
                         af0, af1, af2, af3,
                         __float_as_uint(bp[0]), __float_as_uint(bp[4]));
            }
        }
        // mask + scale
        bool need_mask = (kt >= 2 * qb);
#pragma unroll
        for (int nt = 0; nt < 8; nt++) {
#pragma unroll
            for (int cc = 0; cc < 4; cc++) {
                int row = q0 + row_lo + ((cc >> 1) << 3);
                int col = k0 + nt * 8 + 2 * tig + (cc & 1);
                if (need_mask && col > row) s[nt][cc] = -1e30f;
                else s[nt][cc] *= 0.125f;
            }
        }
        // online softmax (warp-local)
        float mx0 = -1e30f, mx1 = -1e30f;
#pragma unroll
        for (int nt = 0; nt < 8; nt++) {
            mx0 = fmaxf(mx0, fmaxf(s[nt][0], s[nt][1]));
            mx1 = fmaxf(mx1, fmaxf(s[nt][2], s[nt][3]));
        }
        mx0 = fmaxf(mx0, __shfl_xor_sync(0xffffffffu, mx0, 1));
        mx0 = fmaxf(mx0, __shfl_xor_sync(0xffffffffu, mx0, 2));
        mx1 = fmaxf(mx1, __shfl_xor_sync(0xffffffffu, mx1, 1));
        mx1 = fmaxf(mx1, __shfl_xor_sync(0xffffffffu, mx1, 2));
        float mn0 = fmaxf(m0, mx0), mn1 = fmaxf(m1, mx1);
        float a0 = __expf(m0 - mn0), a1 = __expf(m1 - mn1);
        m0 = mn0; m1 = mn1;
        float rs0 = 0.f, rs1 = 0.f;
#pragma unroll
        for (int nt = 0; nt < 8; nt++) {
            s[nt][0] = __expf(s[nt][0] - mn0); rs0 += s[nt][0];
            s[nt][1] = __expf(s[nt][1] - mn0); rs0 += s[nt][1];
            s[nt][2] = __expf(s[nt][2] - mn1); rs1 += s[nt][2];
            s[nt][3] = __expf(s[nt][3] - mn1); rs1 += s[nt][3];
        }
        rs0 += __shfl_xor_sync(0xffffffffu, rs0, 1);
        rs0 += __shfl_xor_sync(0xffffffffu, rs0, 2);
        rs1 += __shfl_xor_sync(0xffffffffu, rs1, 1);
        rs1 += __shfl_xor_sync(0xffffffffu, rs1, 2);
        l0 = l0 * a0 + rs0; l1 = l1 * a1 + rs1;
#pragma unroll
        for (int nt = 0; nt < 8; nt++) {
            acc[nt][0] *= a0; acc[nt][1] *= a0;
            acc[nt][2] *= a1; acc[nt][3] *= a1;
        }
        // store P (own-warp rows only; raw floats)
#pragma unroll
        for (int nt = 0; nt < 8; nt++) {
            int col = nt * 8 + 2 * tig;
            *(float2*)&Ps[row_lo * AST + col] = make_float2(s[nt][0], s[nt][1]);
            *(float2*)&Ps[(row_lo + 8) * AST + col] = make_float2(s[nt][2], s[nt][3]);
        }
        __syncwarp();
        // acc += P @ V
#pragma unroll
        for (int ksl = 0; ksl < 8; ksl++) {
            int kk = ksl * 8;
            const float* ap = &Ps[row_lo * AST + kk + tig];
            unsigned af0 = __float_as_uint(ap[0]);
            unsigned af1 = __float_as_uint(ap[8 * AST]);
            unsigned af2 = __float_as_uint(ap[4]);
            unsigned af3 = __float_as_uint(ap[8 * AST + 4]);
#pragma unroll
            for (int nt = 0; nt < 8; nt++) {
                const float* bp = &Vs[(kk + tig) * AST + nt * 8 + gid];
                mma_tf32(acc[nt][0], acc[nt][1], acc[nt][2], acc[nt][3],
                         af0, af1, af2, af3,
                         __float_as_uint(bp[0]), __float_as_uint(bp[4 * AST]));
            }
        }
        __syncthreads();
    }
    float inv0 = 1.f / l0, inv1 = 1.f / l1;
    size_t obase = (size_t)(b * Lseq) * Dm + h * 64;
    int grow = q0 + row_lo;
#pragma unroll
    for (int nt = 0; nt < 8; nt++) {
        int col = nt * 8 + 2 * tig;
        *(float2*)&out[obase + (size_t)grow * Dm + col] =
            make_float2(acc[nt][0] * inv0, acc[nt][1] * inv0);
        *(float2*)&out[obase + (size_t)(grow + 8) * Dm + col] =
            make_float2(acc[nt][2] * inv1, acc[nt][3] * inv1);
    }
}

// ---------------- small SGEMM (for Wbeta, N=16) ----------------
__global__ void gemm128(const float* __restrict__ A, const float* __restrict__ Bm,
                        float* __restrict__ C, int M, int N, int K) {
    __shared__ float As[16][128];
    __shared__ float Bs[16][64];
    int tid = threadIdx.x;
    int tx = tid & 15, ty = tid >> 4;
    int m0 = blockIdx.y * 128, n0 = blockIdx.x * 64;
    int arow = tid >> 2, ak4 = (tid & 3) * 4, brow = tid >> 4, bc4 = (tid & 15) * 4;
    float acc[8][4];
#pragma unroll
    for (int i = 0; i < 8; i++)
#pragma unroll
        for (int j = 0; j < 4; j++) acc[i][j] = 0.f;
    for (int kk = 0; kk < K; kk += 16) {
#pragma unroll
        for (int half = 0; half < 2; half++) {
            int r = arow + half * 64;
            float4 a4 = *(const float4*)&A[(size_t)(m0 + r) * K + kk + ak4];
            As[ak4+0][r] = a4.x; As[ak4+1][r] = a4.y; As[ak4+2][r] = a4.z; As[ak4+3][r] = a4.w;
        }
        if (n0 + bc4 < N)
            *(float4*)&Bs[brow][bc4] = *(const float4*)&Bm[(size_t)(kk + brow) * N + n0 + bc4];
        else
            *(float4*)&Bs[brow][bc4] = make_float4(0.f, 0.f, 0.f, 0.f);
        __syncthreads();
#pragma unroll
        for (int k2 = 0; k2 < 16; k2++) {
            float4 b4 = *(float4*)&Bs[k2][tx * 4];
            float4 aa = *(float4*)&As[k2][ty * 8];
            float4 ab = *(float4*)&As[k2][ty * 8 + 4];
            float av[8] = {aa.x, aa.y, aa.z, aa.w, ab.x, ab.y, ab.z, ab.w};
            float bv[4] = {b4.x, b4.y, b4.z, b4.w};
#pragma unroll
            for (int i = 0; i < 8; i++)
#pragma unroll
                for (int j = 0; j < 4; j++) acc[i][j] += av[i] * bv[j];
        }
        __syncthreads();
    }
    if (n0 + tx * 4 < N)
#pragma unroll
        for (int i = 0; i < 8; i++)
            *(float4*)&C[(size_t)(m0 + ty * 8 + i) * N + n0 + tx * 4] =
                make_float4(acc[i][0], acc[i][1], acc[i][2], acc[i][3]);
}

// ---------------- conv + k-normalize ----------------
__global__ void conv_kernel(const float* __restrict__ dqr, const float* __restrict__ dkr,
                            const float* __restrict__ cqw, const float* __restrict__ cqb,
                            const float* __restrict__ ckw, const float* __restrict__ ckb,
                            float* __restrict__ dq, float* __restrict__ dk) {
    int bt = blockIdx.x, t = bt & (Lseq - 1), tid = threadIdx.x, c0 = tid * 4;
    float xq[4][4], xk[4][4];
#pragma unroll
    for (int j = 0; j < 4; j++) {
        if (t - 3 + j >= 0) {
            float4 a = *(const float4*)&dqr[(size_t)(bt - 3 + j) * Dm + c0];
            xq[j][0] = a.x; xq[j][1] = a.y; xq[j][2] = a.z; xq[j][3] = a.w;
            float4 b = *(const float4*)&dkr[(size_t)(bt - 3 + j) * Dm + c0];
            xk[j][0] = b.x; xk[j][1] = b.y; xk[j][2] = b.z; xk[j][3] = b.w;
        } else {
#pragma unroll
            for (int u = 0; u < 4; u++) { xq[j][u] = 0.f; xk[j][u] = 0.f; }
        }
    }
    float4 qb4 = *(const float4*)&cqb[c0];
    float4 kb4 = *(const float4*)&ckb[c0];
    float qbv[4] = {qb4.x, qb4.y, qb4.z, qb4.w}, kbv[4] = {kb4.x, kb4.y, kb4.z, kb4.w};
    float oq[4], ok[4];
#pragma unroll
    for (int u = 0; u < 4; u++) {
        float4 wq = *(const float4*)&cqw[(c0 + u) * 4];
        float4 wk = *(const float4*)&ckw[(c0 + u) * 4];
        oq[u] = qbv[u] + wq.x*xq[0][u] + wq.y*xq[1][u] + wq.z*xq[2][u] + wq.w*xq[3][u];
        ok[u] = kbv[u] + wk.x*xk[0][u] + wk.y*xk[1][u] + wk.z*xk[2][u] + wk.w*xk[3][u];
    }
    *(float4*)&dq[(size_t)bt * Dm + c0] = make_float4(oq[0], oq[1], oq[2], oq[3]);
    float ss = ok[0]*ok[0] + ok[1]*ok[1] + ok[2]*ok[2] + ok[3]*ok[3];
    ss += __shfl_xor_sync(0xffffffffu, ss, 1, 16);
    ss += __shfl_xor_sync(0xffffffffu, ss, 2, 16);
    ss += __shfl_xor_sync(0xffffffffu, ss, 4, 16);
    ss += __shfl_xor_sync(0xffffffffu, ss, 8, 16);
    float rn = 1.f / fmaxf(sqrtf(ss), 1e-12f);
    *(float4*)&dk[(size_t)bt * Dm + c0] = make_float4(ok[0]*rn, ok[1]*rn, ok[2]*rn, ok[3]*rn);
}

// ---------------- sequential delta scan ----------------
__global__ void scan_kernel(const float* __restrict__ dq, const float* __restrict__ dk,
                            const float* __restrict__ dv, const float* __restrict__ beta_pre,
                            const float* __restrict__ bbeta,
                            float* __restrict__ ys, float* __restrict__ outS,
                            float* __restrict__ outZ) {
    int bh = blockIdx.x, b = bh >> 4, h = bh & 15;
    int tid = threadIdx.x;
    int r = tid >> 2, qq = tid & 3, c0 = qq * 16;
    int lane = tid & 63, g = tid >> 6;
    __shared__ float qs[64], ks[64], vs[64], zs[64];
    __shared__ float red[8];
    __shared__ float sbeta;
    float S[16];
#pragma unroll
    for (int j = 0; j < 16; j++) S[j] = 0.f;
    if (tid < 64) zs[tid] = 0.f;
    size_t rowbase = (size_t)(b * Lseq) * Dm + (size_t)h * 64;
    size_t betabase = (size_t)(b * Lseq) * Hh + h;
    float pre = 0.f;
    if (g == 0) pre = dq[rowbase + lane];
    else if (g == 1) pre = dk[rowbase + lane];
    else if (g == 2) pre = dv[rowbase + lane];
    else if (lane == 0) pre = beta_pre[betabase] + bbeta[h];
    for (int t = 0; t < Lseq; t++) {
        if (g == 0) qs[lane] = pre;
        else if (g == 1) ks[lane] = pre;
        else if (g == 2) vs[lane] = pre;
        else if (lane == 0) sbeta = 1.f / (1.f + __expf(-pre));
        __syncthreads();
        if (t + 1 < Lseq) {
            size_t row = rowbase + (size_t)(t + 1) * Dm;
            if (g == 0) pre = dq[row + lane];
            else if (g == 1) pre = dk[row + lane];
            else if (g == 2) pre = dv[row + lane];
            else if (lane == 0) pre = beta_pre[betabase + (size_t)(t + 1) * Hh] + bbeta[h];
        }
        float accy = 0.f, acco = 0.f;
#pragma unroll
        for (int j = 0; j < 16; j += 4) {
            float4 q4 = *(float4*)&qs[c0 + j];
            float4 k4 = *(float4*)&ks[c0 + j];
            accy += S[j]*q4.x + S[j+1]*q4.y + S[j+2]*q4.z + S[j+3]*q4.w;
            acco += S[j]*k4.x + S[j+1]*k4.y + S[j+2]*k4.z + S[j+3]*k4.w;
        }
        accy += __shfl_xor_sync(0xffffffffu, accy, 1);
        accy += __shfl_xor_sync(0xffffffffu, accy, 2);
        acco += __shfl_xor_sync(0xffffffffu, acco, 1);
        acco += __shfl_xor_sync(0xffffffffu, acco, 2);
        float dp = (tid < 64) ? zs[tid] * qs[tid] : 0.f;
#pragma unroll
        for (int off = 16; off >= 1; off >>= 1) dp += __shfl_xor_sync(0xffffffffu, dp, off);
        if ((tid & 31) == 0) red[tid >> 5] = dp;
        __syncthreads();
        float denom = red[0] + red[1] + 1e-6f;
        float bet = sbeta;
        float delta = vs[r] - acco;
        if (qq == 0) ys[rowbase + (size_t)t * Dm + r] = accy / denom;
        float bd = bet * delta;
#pragma unroll
        for (int j = 0; j < 16; j += 4) {
            float4 k4 = *(float4*)&ks[c0 + j];
            S[j] += bd*k4.x; S[j+1] += bd*k4.y; S[j+2] += bd*k4.z; S[j+3] += bd*k4.w;
        }
        if (tid < 64) zs[tid] += bet * ks[tid];
        __syncthreads();
    }
    size_t sb2 = (size_t)bh * 4096;
#pragma unroll
    for (int j = 0; j < 16; j++) outS[sb2 + (size_t)r * 64 + c0 + j] = S[j];
    if (tid < 64) outZ[(size_t)bh * 64 + tid] = zs[tid];
}

// ---------------- layernorm ----------------
__global__ void ln_kernel(float* __restrict__ x, const float* __restrict__ gw,
                          const float* __restrict__ bw) {
    __shared__ float rs[8], rq[8];
    int row = blockIdx.x, tid = threadIdx.x;
    float* xr = x + (size_t)row * Dm;
    float4 v = *(float4*)&xr[tid * 4];
    float s = v.x + v.y + v.z + v.w;
    float s2 = v.x*v.x + v.y*v.y + v.z*v.z + v.w*v.w;
#pragma unroll
    for (int off = 16; off >= 1; off >>= 1) {
        s  += __shfl_xor_sync(0xffffffffu, s, off);
        s2 += __shfl_xor_sync(0xffffffffu, s2, off);
    }
    if ((tid & 31) == 0) { rs[tid >> 5] = s; rq[tid >> 5] = s2; }
    __syncthreads();
    float tot = 0.f, tot2 = 0.f;
#pragma unroll
    for (int w = 0; w < 8; w++) { tot += rs[w]; tot2 += rq[w]; }
    float mean = tot * (1.f / 1024.f);
    float var = tot2 * (1.f / 1024.f) - mean * mean;
    float rstd = rsqrtf(var + 1e-5f);
    float4 g4 = *(const float4*)&gw[tid * 4];
    float4 b4 = *(const float4*)&bw[tid * 4];
    v.x = (v.x - mean) * rstd * g4.x + b4.x;
    v.y = (v.y - mean) * rstd * g4.y + b4.y;
    v.z = (v.z - mean) * rstd * g4.z + b4.z;
    v.w = (v.w - mean) * rstd * g4.w + b4.w;
    *(float4*)&xr[tid * 4] = v;
}

// ---------------- gate fusion ----------------
__global__ void gate_kernel(const float* __restrict__ gp, const float* __restrict__ bg,
                            const float* __restrict__ fl, const float* __restrict__ dl,
                            float* __restrict__ out) {
    int row = blockIdx.x, tid = threadIdx.x;
    size_t i = (size_t)row * Dm + tid * 4;
    float4 gpv = *(const float4*)&gp[i];
    float4 bgv = *(const float4*)&bg[tid * 4];
    float4 flv = *(const float4*)&fl[i];
    float4 dlv = *(const float4*)&dl[i];
    float4 o;
    float g0 = 1.f/(1.f+__expf(-(gpv.x+bgv.x))); o.x = g0*flv.x + (1.f-g0)*dlv.x;
    float g1 = 1.f/(1.f+__expf(-(gpv.y+bgv.y))); o.y = g1*flv.y + (1.f-g1)*dlv.y;
    float g2 = 1.f/(1.f+__expf(-(gpv.z+bgv.z))); o.z = g2*flv.z + (1.f-g2)*dlv.z;
    float g3 = 1.f/(1.f+__expf(-(gpv.w+bgv.w))); o.w = g3*flv.w + (1.f-g3)*dlv.w;
    *(float4*)&out[i] = o;
}

// ---------------- launcher (dual-stream: delta branch overlaps attention branch) ----------------
extern "C" void kernel_launch(void* const* d_in, const int* in_sizes, int n_in,
                              void* d_out, int out_size) {
    const float* x     = (const float*)d_in[0];
    const float* Wqkv  = (const float*)d_in[1];
    const float* Wout  = (const float*)d_in[2];
    const float* Wgate = (const float*)d_in[3];
    const float* bgate = (const float*)d_in[4];
    const float* fn_g  = (const float*)d_in[5];
    const float* fn_b  = (const float*)d_in[6];
    const float* dn_g  = (const float*)d_in[7];
    const float* dn_b  = (const float*)d_in[8];
    const float* dWq   = (const float*)d_in[9];
    const float* dWk   = (const float*)d_in[10];
    const float* dWv   = (const float*)d_in[11];
    const float* dWo   = (const float*)d_in[12];
    const float* Wbeta = (const float*)d_in[13];
    const float* bbeta = (const float*)d_in[14];
    const float* cq_w  = (const float*)d_in[15];
    const float* cq_b  = (const float*)d_in[16];
    const float* ck_w  = (const float*)d_in[17];
    const float* ck_b  = (const float*)d_in[18];
    const float* ln_g  = (const float*)d_in[19];
    const float* ln_b  = (const float*)d_in[20];
    float* out = (float*)d_out;

    float *p_qkv, *p_attn, *p_flash, *p_dqr, *p_dkr, *p_dq, *p_dk, *p_dv;
    float *p_beta, *p_ys, *p_delta, *p_gate;
    cudaGetSymbolAddress((void**)&p_qkv,  g_qkv);
    cudaGetSymbolAddress((void**)&p_attn, g_attn);
    cudaGetSymbolAddress((void**)&p_flash,g_flash);
    cudaGetSymbolAddress((void**)&p_dqr,  g_dqr);
    cudaGetSymbolAddress((void**)&p_dkr,  g_dkr);
    cudaGetSymbolAddress((void**)&p_dq,   g_dq);
    cudaGetSymbolAddress((void**)&p_dk,   g_dk);
    cudaGetSymbolAddress((void**)&p_dv,   g_dv);
    cudaGetSymbolAddress((void**)&p_beta, g_beta);
    cudaGetSymbolAddress((void**)&p_ys,   g_ys);
    cudaGetSymbolAddress((void**)&p_delta,g_delta);
    cudaGetSymbolAddress((void**)&p_gate, g_gate);

    float* pS = (out_size >= 4327424) ? out + 4194304 : p_qkv;
    float* pZ = (out_size >= 4327424) ? out + 4325376 : p_qkv + 4096;

    static cudaStream_t s1 = nullptr;
    static cudaEvent_t e1 = nullptr, e2 = nullptr;
    if (!s1) {
        cudaStreamCreateWithFlags(&s1, cudaStreamNonBlocking);
        cudaEventCreateWithFlags(&e1, cudaEventDisableTiming);
        cudaEventCreateWithFlags(&e2, cudaEventDisableTiming);
    }

    cudaFuncSetAttribute(gemm_tf32_t<false>, cudaFuncAttributeMaxDynamicSharedMemorySize, GEMM_SMEM_FAST);
    cudaFuncSetAttribute(gemm_tf32_t<true>,  cudaFuncAttributeMaxDynamicSharedMemorySize, GEMM_SMEM_P3);
    cudaFuncSetAttribute(attn_mma, cudaFuncAttributeMaxDynamicSharedMemorySize, ATTN_SMEM);

    // projections (stream 0)
    gemm_tf32_t<false><<<dim3(24, 32), 256, GEMM_SMEM_FAST>>>(x, Wqkv,  p_qkv,  BL, 3 * Dm, Dm);
    gemm_tf32_t<true><<<dim3(8, 32), 256, GEMM_SMEM_P3>>>(x, dWq,   p_dqr,  BL, Dm, Dm);
    gemm_tf32_t<true><<<dim3(8, 32), 256, GEMM_SMEM_P3>>>(x, dWk,   p_dkr,  BL, Dm, Dm);
    gemm_tf32_t<true><<<dim3(8, 32), 256, GEMM_SMEM_P3>>>(x, dWv,   p_dv,   BL, Dm, Dm);
    gemm_tf32_t<false><<<dim3(8, 32), 256, GEMM_SMEM_FAST>>>(x, Wgate, p_gate, BL, Dm, Dm);
    gemm128<<<dim3(1, 32), 256>>>(x, Wbeta, p_beta, BL, Hh, Dm);
    conv_kernel<<<BL, 256>>>(p_dqr, p_dkr, cq_w, cq_b, ck_w, ck_b, p_dq, p_dk);

    // fork: delta branch on s1 (scan is low-occupancy; overlaps attention chain)
    cudaEventRecord(e1, 0);
    cudaStreamWaitEvent(s1, e1, 0);
    scan_kernel<<<32, 256, 0, s1>>>(p_dq, p_dk, p_dv, p_beta, bbeta, p_ys, pS, pZ);
    gemm_tf32_t<false><<<dim3(8, 32), 256, GEMM_SMEM_FAST, s1>>>(p_ys, dWo, p_delta, BL, Dm, Dm);
    ln_kernel<<<BL, 256, 0, s1>>>(p_delta, ln_g, ln_b);
    ln_kernel<<<BL, 256, 0, s1>>>(p_delta, dn_g, dn_b);
    cudaEventRecord(e2, s1);

    // attention branch on stream 0
    attn_mma<<<dim3(16, 32), 256, ATTN_SMEM>>>(p_qkv, p_attn);
    gemm_tf32_t<false><<<dim3(8, 32), 256, GEMM_SMEM_FAST>>>(p_attn, Wout, p_flash, BL, Dm, Dm);
    ln_kernel<<<BL, 256>>>(p_flash, fn_g, fn_b);

    // join + gate
    cudaStreamWaitEvent(0, e2, 0);
    gate_kernel<<<BL, 256>>>(p_gate, bgate, p_flash, p_delta, out);
}

// round 9
// speedup vs baseline: 1.9805x; 1.0035x over previous
#include <cuda_runtime.h>
#include <math.h>
#include <stdint.h>

#define Bsz 2
#define Lseq 2048
#define Dm 1024
#define Hh 16
#define BL (Bsz*Lseq)   // 4096

// ---------------- scratch ----------------
__device__ float g_qkv[BL*3*Dm];
__device__ float g_attn[BL*Dm];
__device__ float g_flash[BL*Dm];
__device__ float g_dqr[BL*Dm];
__device__ float g_dkr[BL*Dm];
__device__ float g_dq[BL*Dm];
__device__ float g_dk[BL*Dm];
__device__ float g_dv[BL*Dm];
__device__ float g_beta[BL*Hh];
__device__ float g_ys[BL*Dm];
__device__ float g_delta[BL*Dm];
__device__ float g_gate[BL*Dm];

// ---------------- tf32 helpers ----------------
__device__ __forceinline__ float f2tf32(float x) {
    float r;
    asm("cvt.rna.tf32.f32 %0, %1;" : "=f"(r) : "f"(x));
    return r;
}
__device__ __forceinline__ void mma_tf32(float& c0, float& c1, float& c2, float& c3,
                                         unsigned a0, unsigned a1, unsigned a2, unsigned a3,
                                         unsigned b0, unsigned b1) {
    asm volatile("mma.sync.aligned.m16n8k8.row.col.f32.tf32.tf32.f32 "
                 "{%0,%1,%2,%3}, {%4,%5,%6,%7}, {%8,%9}, {%0,%1,%2,%3};"
                 : "+f"(c0), "+f"(c1), "+f"(c2), "+f"(c3)
                 : "r"(a0), "r"(a1), "r"(a2), "r"(a3), "r"(b0), "r"(b1));
}

// ---------------- tf32 tensor-core GEMM (optionally 3xTF32 precise) ----------------
#define AS_STRIDE 36
#define BS_STRIDE 132
#define ABUF (128*AS_STRIDE)
#define BBUF (32*BS_STRIDE)
#define GEMM_SMEM_FAST ((2*ABUF + 2*BBUF) * 4)
#define GEMM_SMEM_P3   ((4*ABUF + 4*BBUF) * 4)

template<bool P3>
__device__ __forceinline__ void stage_tile(float* Ah, float* Al, float* Bh, float* Bl,
                                           const float4* ra, const float4* rb, int tid) {
#pragma unroll
    for (int i = 0; i < 4; i++) {
        int e = tid + i * 256;
        int ar = e >> 3, ac = (e & 7) * 4;
        float* ap = &Ah[ar * AS_STRIDE + ac];
        float4 v = ra[i];
        float h0 = f2tf32(v.x), h1 = f2tf32(v.y), h2 = f2tf32(v.z), h3 = f2tf32(v.w);
        ap[0] = h0; ap[1] = h1; ap[2] = h2; ap[3] = h3;
        if (P3) {
            float* al = &Al[ar * AS_STRIDE + ac];
            al[0] = f2tf32(v.x - h0); al[1] = f2tf32(v.y - h1);
            al[2] = f2tf32(v.z - h2); al[3] = f2tf32(v.w - h3);
        }
        int br = e >> 5, bc = (e & 31) * 4;
        float4 w = rb[i];
        float g0 = f2tf32(w.x), g1 = f2tf32(w.y), g2 = f2tf32(w.z), g3 = f2tf32(w.w);
        *(float4*)&Bh[br * BS_STRIDE + bc] = make_float4(g0, g1, g2, g3);
        if (P3) {
            *(float4*)&Bl[br * BS_STRIDE + bc] =
                make_float4(f2tf32(w.x - g0), f2tf32(w.y - g1),
                            f2tf32(w.z - g2), f2tf32(w.w - g3));
        }
    }
}

template<bool P3>
__global__ void gemm_tf32_t(const float* __restrict__ A, const float* __restrict__ B,
                            float* __restrict__ C, int M, int N, int K) {
    extern __shared__ float sm[];
    float* Ah = sm;
    float* Bh = sm + 2 * ABUF;
    float* Al = P3 ? sm + 2 * ABUF + 2 * BBUF : sm;
    float* Bl = P3 ? Al + 2 * ABUF : sm;

    int tid = threadIdx.x;
    int warp = tid >> 5, lane = tid & 31;
    int gid = lane >> 2, tig = lane & 3;
    int warp_m = (warp >> 2) * 64;
    int warp_n = (warp & 3) * 32;
    int m0 = blockIdx.y * 128, n0 = blockIdx.x * 128;

    float acc[4][4][4];
#pragma unroll
    for (int i = 0; i < 4; i++)
#pragma unroll
        for (int j = 0; j < 4; j++)
#pragma unroll
            for (int u = 0; u < 4; u++) acc[i][j][u] = 0.f;

    float4 ra[4], rb[4];
    int kt_total = K >> 5;

#pragma unroll
    for (int i = 0; i < 4; i++) {
        int e = tid + i * 256;
        int ar = e >> 3, ac = (e & 7) * 4;
        ra[i] = *(const float4*)&A[(size_t)(m0 + ar) * K + ac];
        int br = e >> 5, bc = (e & 31) * 4;
        rb[i] = *(const float4*)&B[(size_t)br * N + n0 + bc];
    }
    stage_tile<P3>(Ah, Al, Bh, Bl, ra, rb, tid);
    __syncthreads();

    for (int t = 0; t < kt_total; t++) {
        int cur = t & 1;
        float* Ahc = Ah + cur * ABUF;
        float* Bhc = Bh + cur * BBUF;
        float* Alc = Al + cur * ABUF;
        float* Blc = Bl + cur * BBUF;

        if (t + 1 < kt_total) {
            int kk = (t + 1) << 5;
#pragma unroll
            for (int i = 0; i < 4; i++) {
                int e = tid + i * 256;
                int ar = e >> 3, ac = (e & 7) * 4;
                ra[i] = *(const float4*)&A[(size_t)(m0 + ar) * K + kk + ac];
                int br = e >> 5, bc = (e & 31) * 4;
                rb[i] = *(const float4*)&B[(size_t)(kk + br) * N + n0 + bc];
            }
        }

#pragma unroll
        for (int ks = 0; ks < 4; ks++) {
            int k0 = ks * 8;
            unsigned afh[4][4], bfh[4][2];
            unsigned afl[4][4], bfl[4][2];
#pragma unroll
            for (int mt = 0; mt < 4; mt++) {
                int r = warp_m + mt * 16 + gid;
                const float* ap = &Ahc[r * AS_STRIDE + k0 + tig];
                afh[mt][0] = __float_as_uint(ap[0]);
                afh[mt][1] = __float_as_uint(ap[AS_STRIDE * 8]);
                afh[mt][2] = __float_as_uint(ap[4]);
                afh[mt][3] = __float_as_uint(ap[AS_STRIDE * 8 + 4]);
                if (P3) {
                    const float* al = &Alc[r * AS_STRIDE + k0 + tig];
                    afl[mt][0] = __float_as_uint(al[0]);
                    afl[mt][1] = __float_as_uint(al[AS_STRIDE * 8]);
                    afl[mt][2] = __float_as_uint(al[4]);
                    afl[mt][3] = __float_as_uint(al[AS_STRIDE * 8 + 4]);
                }
            }
#pragma unroll
            for (int nt = 0; nt < 4; nt++) {
                int c = warp_n + nt * 8 + gid;
                const float* bp = &Bhc[(k0 + tig) * BS_STRIDE + c];
                bfh[nt][0] = __float_as_uint(bp[0]);
                bfh[nt][1] = __float_as_uint(bp[BS_STRIDE * 4]);
                if (P3) {
                    const float* bl = &Blc[(k0 + tig) * BS_STRIDE + c];
                    bfl[nt][0] = __float_as_uint(bl[0]);
                    bfl[nt][1] = __float_as_uint(bl[BS_STRIDE * 4]);
                }
            }
#pragma unroll
            for (int mt = 0; mt < 4; mt++)
#pragma unroll
                for (int nt = 0; nt < 4; nt++) {
                    if (P3) {
                        mma_tf32(acc[mt][nt][0], acc[mt][nt][1], acc[mt][nt][2], acc[mt][nt][3],
                                 afh[mt][0], afh[mt][1], afh[mt][2], afh[mt][3],
                                 bfl[nt][0], bfl[nt][1]);
                        mma_tf32(acc[mt][nt][0], acc[mt][nt][1], acc[mt][nt][2], acc[mt][nt][3],
                                 afl[mt][0], afl[mt][1], afl[mt][2], afl[mt][3],
                                 bfh[nt][0], bfh[nt][1]);
                    }
                    mma_tf32(acc[mt][nt][0], acc[mt][nt][1], acc[mt][nt][2], acc[mt][nt][3],
                             afh[mt][0], afh[mt][1], afh[mt][2], afh[mt][3],
                             bfh[nt][0], bfh[nt][1]);
                }
        }

        if (t + 1 < kt_total) {
            int nxt = (t + 1) & 1;
            stage_tile<P3>(Ah + nxt * ABUF, Al + nxt * ABUF,
                           Bh + nxt * BBUF, Bl + nxt * BBUF, ra, rb, tid);
        }
        __syncthreads();
    }

#pragma unroll
    for (int mt = 0; mt < 4; mt++) {
#pragma unroll
        for (int nt = 0; nt < 4; nt++) {
            int row = m0 + warp_m + mt * 16 + gid;
            int col = n0 + warp_n + nt * 8 + 2 * tig;
            *(float2*)&C[(size_t)row * N + col] =
                make_float2(acc[mt][nt][0], acc[mt][nt][1]);
            *(float2*)&C[(size_t)(row + 8) * N + col] =
                make_float2(acc[mt][nt][2], acc[mt][nt][3]);
        }
    }
}

// ---------------- mma-based causal flash attention (single-pass tf32) ----------------
#define AST 68
#define ATTN_SMEM (384 * AST * 4)

__global__ void __launch_bounds__(256, 2) attn_mma(const float* __restrict__ qkv,
                                                   float* __restrict__ out) {
    extern __shared__ float sm[];
    float* Qs = sm;
    float* Ks = sm + 128 * AST;
    float* Vs = sm + 192 * AST;
    float* Ps = sm + 256 * AST;

    int qb = (int)gridDim.x - 1 - (int)blockIdx.x;
    int bh = blockIdx.y;
    int b = bh >> 4, h = bh & 15;
    int tid = threadIdx.x, warp = tid >> 5, lane = tid & 31;
    int gid = lane >> 2, tig = lane & 3;
    size_t base = (size_t)(b * Lseq) * 3072 + h * 64;
    int q0 = qb * 128;
    int row_lo = warp * 16 + gid;

    {
        int r = tid >> 1, dc = (tid & 1) * 32;
        const float4* src = (const float4*)&qkv[base + (size_t)(q0 + r) * 3072 + dc];
        float4* dst = (float4*)&Qs[r * AST + dc];
#pragma unroll
        for (int i = 0; i < 8; i++) dst[i] = src[i];
    }
    float acc[8][4];
#pragma unroll
    for (int nt = 0; nt < 8; nt++)
#pragma unroll
        for (int cc = 0; cc < 4; cc++) acc[nt][cc] = 0.f;
    float m0 = -1e30f, m1 = -1e30f, l0 = 0.f, l1 = 0.f;
    __syncthreads();

    int ktend = 2 * qb + 1;
    for (int kt = 0; kt <= ktend; kt++) {
        int k0 = kt * 64;
        {
            int r = tid >> 2, dc = (tid & 3) * 16;
            const float4* ksrc = (const float4*)&qkv[base + 1024 + (size_t)(k0 + r) * 3072 + dc];
            const float4* vsrc = (const float4*)&qkv[base + 2048 + (size_t)(k0 + r) * 3072 + dc];
            float4* kdst = (float4*)&Ks[r * AST + dc];
            float4* vdst = (float4*)&Vs[r * AST + dc];
#pragma unroll
            for (int i = 0; i < 4; i++) { kdst[i] = ksrc[i]; vdst[i] = vsrc[i]; }
        }
        __syncthreads();

        float s[8][4];
#pragma unroll
        for (int nt = 0; nt < 8; nt++)
#pragma unroll
            for (int cc = 0; cc < 4; cc++) s[nt][cc] = 0.f;
#pragma unroll
        for (int ksl = 0; ksl < 8; ksl++) {
            int kk = ksl * 8;
            const float* ap = &Qs[row_lo * AST + kk + tig];
            unsigned af0 = __float_as_uint(ap[0]);
            unsigned af1 = __float_as_uint(ap[8 * AST]);
            unsigned af2 = __float_as_uint(ap[4]);
            unsigned af3 = __float_as_uint(ap[8 * AST + 4]);
#pragma unroll
            for (int nt = 0; nt < 8; nt++) {
                const float* bp = &Ks[(nt * 8 + gid) * AST + kk + tig];
                mma_tf32(s[nt][0], s[nt][1], s[nt][2], s[nt][3],
                         af0, af1, af2, af3,
                         __float_as_uint(bp[0]), __float_as_uint(bp[4]));
            }
        }
        bool need_mask = (kt >= 2 * qb);
#pragma unroll
        for (int nt = 0; nt < 8; nt++) {
#pragma unroll
            for (int cc = 0; cc < 4; cc++) {
                int row = q0 + row_lo + ((cc >> 1) << 3);
                int col = k0 + nt * 8 + 2 * tig + (cc & 1);
                if (need_mask && col > row) s[nt][cc] = -1e30f;
                else s[nt][cc] *= 0.125f;
            }
        }
        float mx0 = -1e30f, mx1 = -1e30f;
#pragma unroll
        for (int nt = 0; nt < 8; nt++) {
            mx0 = fmaxf(mx0, fmaxf(s[nt][0], s[nt][1]));
            mx1 = fmaxf(mx1, fmaxf(s[nt][2], s[nt][3]));
        }
        mx0 = fmaxf(mx0, __shfl_xor_sync(0xffffffffu, mx0, 1));
        mx0 = fmaxf(mx0, __shfl_xor_sync(0xffffffffu, mx0, 2));
        mx1 = fmaxf(mx1, __shfl_xor_sync(0xffffffffu, mx1, 1));
        mx1 = fmaxf(mx1, __shfl_xor_sync(0xffffffffu, mx1, 2));
        float mn0 = fmaxf(m0, mx0), mn1 = fmaxf(m1, mx1);
        float a0 = __expf(m0 - mn0), a1 = __expf(m1 - mn1);
        m0 = mn0; m1 = mn1;
        float rs0 = 0.f, rs1 = 0.f;
#pragma unroll
        for (int nt = 0; nt < 8; nt++) {
            s[nt][0] = __expf(s[nt][0] - mn0); rs0 += s[nt][0];
            s[nt][1] = __expf(s[nt][1] - mn0); rs0 += s[nt][1];
            s[nt][2] = __expf(s[nt][2] - mn1); rs1 += s[nt][2];
            s[nt][3] = __expf(s[nt][3] - mn1); rs1 += s[nt][3];
        }
        rs0 += __shfl_xor_sync(0xffffffffu, rs0, 1);
        rs0 += __shfl_xor_sync(0xffffffffu, rs0, 2);
        rs1 += __shfl_xor_sync(0xffffffffu, rs1, 1);
        rs1 += __shfl_xor_sync(0xffffffffu, rs1, 2);
        l0 = l0 * a0 + rs0; l1 = l1 * a1 + rs1;
#pragma unroll
        for (int nt = 0; nt < 8; nt++) {
            acc[nt][0] *= a0; acc[nt][1] *= a0;
            acc[nt][2] *= a1; acc[nt][3] *= a1;
        }
#pragma unroll
        for (int nt = 0; nt < 8; nt++) {
            int col = nt * 8 + 2 * tig;
            *(float2*)&Ps[row_lo * AST + col] = make_float2(s[nt][0], s[nt][1]);
            *(float2*)&Ps[(row_lo + 8) * AST + col] = make_float2(s[nt][2], s[nt][3]);
        }
        __syncwarp();
#pragma unroll
        for (int ksl = 0; ksl < 8; ksl++) {
            int kk = ksl * 8;
            const float* ap = &Ps[row_lo * AST + kk + tig];
            unsigned af0 = __float_as_uint(ap[0]);
            unsigned af1 = __float_as_uint(ap[8 * AST]);
            unsigned af2 = __float_as_uint(ap[4]);
            unsigned af3 = __float_as_uint(ap[8 * AST + 4]);
#pragma unroll
            for (int nt = 0; nt < 8; nt++) {
                const float* bp = &Vs[(kk + tig) * AST + nt * 8 + gid];
                mma_tf32(acc[nt][0], acc[nt][1], acc[nt][2], acc[nt][3],
                         af0, af1, af2, af3,
                         __float_as_uint(bp[0]), __float_as_uint(bp[4 * AST]));
            }
        }
        __syncthreads();
    }
    float inv0 = 1.f / l0, inv1 = 1.f / l1;
    size_t obase = (size_t)(b * Lseq) * Dm + h * 64;
    int grow = q0 + row_lo;
#pragma unroll
    for (int nt = 0; nt < 8; nt++) {
        int col = nt * 8 + 2 * tig;
        *(float2*)&out[obase + (size_t)grow * Dm + col] =
            make_float2(acc[nt][0] * inv0, acc[nt][1] * inv0);
        *(float2*)&out[obase + (size_t)(grow + 8) * Dm + col] =
            make_float2(acc[nt][2] * inv1, acc[nt][3] * inv1);
    }
}

// ---------------- small SGEMM (for Wbeta, N=16) ----------------
__global__ void gemm128(const float* __restrict__ A, const float* __restrict__ Bm,
                        float* __restrict__ C, int M, int N, int K) {
    __shared__ float As[16][128];
    __shared__ float Bs[16][64];
    int tid = threadIdx.x;
    int tx = tid & 15, ty = tid >> 4;
    int m0 = blockIdx.y * 128, n0 = blockIdx.x * 64;
    int arow = tid >> 2, ak4 = (tid & 3) * 4, brow = tid >> 4, bc4 = (tid & 15) * 4;
    float acc[8][4];
#pragma unroll
    for (int i = 0; i < 8; i++)
#pragma unroll
        for (int j = 0; j < 4; j++) acc[i][j] = 0.f;
    for (int kk = 0; kk < K; kk += 16) {
#pragma unroll
        for (int half = 0; half < 2; half++) {
            int r = arow + half * 64;
            float4 a4 = *(const float4*)&A[(size_t)(m0 + r) * K + kk + ak4];
            As[ak4+0][r] = a4.x; As[ak4+1][r] = a4.y; As[ak4+2][r] = a4.z; As[ak4+3][r] = a4.w;
        }
        if (n0 + bc4 < N)
            *(float4*)&Bs[brow][bc4] = *(const float4*)&Bm[(size_t)(kk + brow) * N + n0 + bc4];
        else
            *(float4*)&Bs[brow][bc4] = make_float4(0.f, 0.f, 0.f, 0.f);
        __syncthreads();
#pragma unroll
        for (int k2 = 0; k2 < 16; k2++) {
            float4 b4 = *(float4*)&Bs[k2][tx * 4];
            float4 aa = *(float4*)&As[k2][ty * 8];
            float4 ab = *(float4*)&As[k2][ty * 8 + 4];
            float av[8] = {aa.x, aa.y, aa.z, aa.w, ab.x, ab.y, ab.z, ab.w};
            float bv[4] = {b4.x, b4.y, b4.z, b4.w};
#pragma unroll
            for (int i = 0; i < 8; i++)
#pragma unroll
                for (int j = 0; j < 4; j++) acc[i][j] += av[i] * bv[j];
        }
        __syncthreads();
    }
    if (n0 + tx * 4 < N)
#pragma unroll
        for (int i = 0; i < 8; i++)
            *(float4*)&C[(size_t)(m0 + ty * 8 + i) * N + n0 + tx * 4] =
                make_float4(acc[i][0], acc[i][1], acc[i][2], acc[i][3]);
}

// ---------------- conv + k-normalize ----------------
__global__ void conv_kernel(const float* __restrict__ dqr, const float* __restrict__ dkr,
                            const float* __restrict__ cqw, const float* __restrict__ cqb,
                            const float* __restrict__ ckw, const float* __restrict__ ckb,
                            float* __restrict__ dq, float* __restrict__ dk) {
    int bt = blockIdx.x, t = bt & (Lseq - 1), tid = threadIdx.x, c0 = tid * 4;
    float xq[4][4], xk[4][4];
#pragma unroll
    for (int j = 0; j < 4; j++) {
        if (t - 3 + j >= 0) {
            float4 a = *(const float4*)&dqr[(size_t)(bt - 3 + j) * Dm + c0];
            xq[j][0] = a.x; xq[j][1] = a.y; xq[j][2] = a.z; xq[j][3] = a.w;
            float4 b = *(const float4*)&dkr[(size_t)(bt - 3 + j) * Dm + c0];
            xk[j][0] = b.x; xk[j][1] = b.y; xk[j][2] = b.z; xk[j][3] = b.w;
        } else {
#pragma unroll
            for (int u = 0; u < 4; u++) { xq[j][u] = 0.f; xk[j][u] = 0.f; }
        }
    }
    float4 qb4 = *(const float4*)&cqb[c0];
    float4 kb4 = *(const float4*)&ckb[c0];
    float qbv[4] = {qb4.x, qb4.y, qb4.z, qb4.w}, kbv[4] = {kb4.x, kb4.y, kb4.z, kb4.w};
    float oq[4], ok[4];
#pragma unroll
    for (int u = 0; u < 4; u++) {
        float4 wq = *(const float4*)&cqw[(c0 + u) * 4];
        float4 wk = *(const float4*)&ckw[(c0 + u) * 4];
        oq[u] = qbv[u] + wq.x*xq[0][u] + wq.y*xq[1][u] + wq.z*xq[2][u] + wq.w*xq[3][u];
        ok[u] = kbv[u] + wk.x*xk[0][u] + wk.y*xk[1][u] + wk.z*xk[2][u] + wk.w*xk[3][u];
    }
    *(float4*)&dq[(size_t)bt * Dm + c0] = make_float4(oq[0], oq[1], oq[2], oq[3]);
    float ss = ok[0]*ok[0] + ok[1]*ok[1] + ok[2]*ok[2] + ok[3]*ok[3];
    ss += __shfl_xor_sync(0xffffffffu, ss, 1, 16);
    ss += __shfl_xor_sync(0xffffffffu, ss, 2, 16);
    ss += __shfl_xor_sync(0xffffffffu, ss, 4, 16);
    ss += __shfl_xor_sync(0xffffffffu, ss, 8, 16);
    float rn = 1.f / fmaxf(sqrtf(ss), 1e-12f);
    *(float4*)&dk[(size_t)bt * Dm + c0] = make_float4(ok[0]*rn, ok[1]*rn, ok[2]*rn, ok[3]*rn);
}

// ---------------- delta scan: 1 barrier/step, z in registers, quad-only reductions ----------------
__global__ void scan_kernel(const float* __restrict__ dq, const float* __restrict__ dk,
                            const float* __restrict__ dv, const float* __restrict__ beta_pre,
                            const float* __restrict__ bbeta,
                            float* __restrict__ ys, float* __restrict__ outS,
                            float* __restrict__ outZ) {
    int bh = blockIdx.x, b = bh >> 4, h = bh & 15;
    int tid = threadIdx.x;
    int r = tid >> 2, qq = tid & 3, c0 = qq * 16;
    int lane64 = tid & 63, g = tid >> 6;

    __shared__ float qs[2][64], ks[2][64], vs[2][64];
    __shared__ float bpre[2];

    float S[16], z[16];
#pragma unroll
    for (int j = 0; j < 16; j++) { S[j] = 0.f; z[j] = 0.f; }

    size_t rowbase = (size_t)(b * Lseq) * Dm + (size_t)h * 64;
    size_t betabase = (size_t)(b * Lseq) * Hh + h;
    float bb = bbeta[h];

    // stage step 0; prefetch step 1
    if (g == 0) qs[0][lane64] = dq[rowbase + lane64];
    else if (g == 1) ks[0][lane64] = dk[rowbase + lane64];
    else if (g == 2) vs[0][lane64] = dv[rowbase + lane64];
    else if (lane64 == 0) bpre[0] = beta_pre[betabase];
    float pre = 0.f;
    {
        size_t row = rowbase + Dm;
        if (g == 0) pre = dq[row + lane64];
        else if (g == 1) pre = dk[row + lane64];
        else if (g == 2) pre = dv[row + lane64];
        else if (lane64 == 0) pre = beta_pre[betabase + Hh];
    }
    __syncthreads();

    for (int t = 0; t < Lseq; t++) {
        int cur = t & 1, nxt = cur ^ 1;
        // snapshot current step into registers
        float4 q4[4], k4[4];
#pragma unroll
        for (int jj = 0; jj < 4; jj++) {
            q4[jj] = *(float4*)&qs[cur][c0 + jj * 4];
            k4[jj] = *(float4*)&ks[cur][c0 + jj * 4];
        }
        float vr = vs[cur][r];
        float bp = bpre[cur];

        // stage next (from prefetch reg), prefetch t+2
        if (t + 1 < Lseq) {
            if (g == 0) qs[nxt][lane64] = pre;
            else if (g == 1) ks[nxt][lane64] = pre;
            else if (g == 2) vs[nxt][lane64] = pre;
            else if (lane64 == 0) bpre[nxt] = pre;
            if (t + 2 < Lseq) {
                size_t row = rowbase + (size_t)(t + 2) * Dm;
                if (g == 0) pre = dq[row + lane64];
                else if (g == 1) pre = dk[row + lane64];
                else if (g == 2) pre = dv[row + lane64];
                else if (lane64 == 0) pre = beta_pre[betabase + (size_t)(t + 2) * Hh];
            }
        }

        // compute: S·q, S·k, z·q — all reduced with quad shuffles only
        float accy = 0.f, acco = 0.f, dp = 0.f;
#pragma unroll
        for (int jj = 0; jj < 4; jj++) {
            float4 q = q4[jj], k = k4[jj];
            int j = jj * 4;
            accy += S[j]*q.x + S[j+1]*q.y + S[j+2]*q.z + S[j+3]*q.w;
            acco += S[j]*k.x + S[j+1]*k.y + S[j+2]*k.z + S[j+3]*k.w;
            dp   += z[j]*q.x + z[j+1]*q.y + z[j+2]*q.z + z[j+3]*q.w;
        }
        accy += __shfl_xor_sync(0xffffffffu, accy, 1);
        accy += __shfl_xor_sync(0xffffffffu, accy, 2);
        acco += __shfl_xor_sync(0xffffffffu, acco, 1);
        acco += __shfl_xor_sync(0xffffffffu, acco, 2);
        dp   += __shfl_xor_sync(0xffffffffu, dp, 1);
        dp   += __shfl_xor_sync(0xffffffffu, dp, 2);

        float denom = dp + 1e-6f;
        float bet = 1.f / (1.f + __expf(-(bp + bb)));
        float delta = vr - acco;
        if (qq == 0) ys[rowbase + (size_t)t * Dm + r] = accy / denom;

        float bd = bet * delta;
#pragma unroll
        for (int jj = 0; jj < 4; jj++) {
            float4 k = k4[jj];
            int j = jj * 4;
            S[j]   += bd * k.x; S[j+1] += bd * k.y;
            S[j+2] += bd * k.z; S[j+3] += bd * k.w;
            z[j]   += bet * k.x; z[j+1] += bet * k.y;
            z[j+2] += bet * k.z; z[j+3] += bet * k.w;
        }
        __syncthreads();   // staging of t+1 complete; reads of cur done
    }

    size_t sb2 = (size_t)bh * 4096;
#pragma unroll
    for (int j = 0; j < 16; j++) outS[sb2 + (size_t)r * 64 + c0 + j] = S[j];
    if (r == 0)
#pragma unroll
        for (int j = 0; j < 16; j++) outZ[(size_t)bh * 64 + c0 + j] = z[j];
}

// ---------------- layernorm ----------------
__global__ void ln_kernel(float* __restrict__ x, const float* __restrict__ gw,
                          const float* __restrict__ bw) {
    __shared__ float rs[8], rq[8];
    int row = blockIdx.x, tid = threadIdx.x;
    float* xr = x + (size_t)row * Dm;
    float4 v = *(float4*)&xr[tid * 4];
    float s = v.x + v.y + v.z + v.w;
    float s2 = v.x*v.x + v.y*v.y + v.z*v.z + v.w*v.w;
#pragma unroll
    for (int off = 16; off >= 1; off >>= 1) {
        s  += __shfl_xor_sync(0xffffffffu, s, off);
        s2 += __shfl_xor_sync(0xffffffffu, s2, off);
    }
    if ((tid & 31) == 0) { rs[tid >> 5] = s; rq[tid >> 5] = s2; }
    __syncthreads();
    float tot = 0.f, tot2 = 0.f;
#pragma unroll
    for (int w = 0; w < 8; w++) { tot += rs[w]; tot2 += rq[w]; }
    float mean = tot * (1.f / 1024.f);
    float var = tot2 * (1.f / 1024.f) - mean * mean;
    float rstd = rsqrtf(var + 1e-5f);
    float4 g4 = *(const float4*)&gw[tid * 4];
    float4 b4 = *(const float4*)&bw[tid * 4];
    v.x = (v.x - mean) * rstd * g4.x + b4.x;
    v.y = (v.y - mean) * rstd * g4.y + b4.y;
    v.z = (v.z - mean) * rstd * g4.z + b4.z;
    v.w = (v.w - mean) * rstd * g4.w + b4.w;
    *(float4*)&xr[tid * 4] = v;
}

// ---------------- gate fusion ----------------
__global__ void gate_kernel(const float* __restrict__ gp, const float* __restrict__ bg,
                            const float* __restrict__ fl, const float* __restrict__ dl,
                            float* __restrict__ out) {
    int row = blockIdx.x, tid = threadIdx.x;
    size_t i = (size_t)row * Dm + tid * 4;
    float4 gpv = *(const float4*)&gp[i];
    float4 bgv = *(const float4*)&bg[tid * 4];
    float4 flv = *(const float4*)&fl[i];
    float4 dlv = *(const float4*)&dl[i];
    float4 o;
    float g0 = 1.f/(1.f+__expf(-(gpv.x+bgv.x))); o.x = g0*flv.x + (1.f-g0)*dlv.x;
    float g1 = 1.f/(1.f+__expf(-(gpv.y+bgv.y))); o.y = g1*flv.y + (1.f-g1)*dlv.y;
    float g2 = 1.f/(1.f+__expf(-(gpv.z+bgv.z))); o.z = g2*flv.z + (1.f-g2)*dlv.z;
    float g3 = 1.f/(1.f+__expf(-(gpv.w+bgv.w))); o.w = g3*flv.w + (1.f-g3)*dlv.w;
    *(float4*)&out[i] = o;
}

// ---------------- launcher: full dual-stream fork from the top ----------------
extern "C" void kernel_launch(void* const* d_in, const int* in_sizes, int n_in,
                              void* d_out, int out_size) {
    const float* x     = (const float*)d_in[0];
    const float* Wqkv  = (const float*)d_in[1];
    const float* Wout  = (const float*)d_in[2];
    const float* Wgate = (const float*)d_in[3];
    const float* bgate = (const float*)d_in[4];
    const float* fn_g  = (const float*)d_in[5];
    const float* fn_b  = (const float*)d_in[6];
    const float* dn_g  = (const float*)d_in[7];
    const float* dn_b  = (const float*)d_in[8];
    const float* dWq   = (const float*)d_in[9];
    const float* dWk   = (const float*)d_in[10];
    const float* dWv   = (const float*)d_in[11];
    const float* dWo   = (const float*)d_in[12];
    const float* Wbeta = (const float*)d_in[13];
    const float* bbeta = (const float*)d_in[14];
    const float* cq_w  = (const float*)d_in[15];
    const float* cq_b  = (const float*)d_in[16];
    const float* ck_w  = (const float*)d_in[17];
    const float* ck_b  = (const float*)d_in[18];
    const float* ln_g  = (const float*)d_in[19];
    const float* ln_b  = (const float*)d_in[20];
    float* out = (float*)d_out;

    float *p_qkv, *p_attn, *p_flash, *p_dqr, *p_dkr, *p_dq, *p_dk, *p_dv;
    float *p_beta, *p_ys, *p_delta, *p_gate;
    cudaGetSymbolAddress((void**)&p_qkv,  g_qkv);
    cudaGetSymbolAddress((void**)&p_attn, g_attn);
    cudaGetSymbolAddress((void**)&p_flash,g_flash);
    cudaGetSymbolAddress((void**)&p_dqr,  g_dqr);
    cudaGetSymbolAddress((void**)&p_dkr,  g_dkr);
    cudaGetSymbolAddress((void**)&p_dq,   g_dq);
    cudaGetSymbolAddress((void**)&p_dk,   g_dk);
    cudaGetSymbolAddress((void**)&p_dv,   g_dv);
    cudaGetSymbolAddress((void**)&p_beta, g_beta);
    cudaGetSymbolAddress((void**)&p_ys,   g_ys);
    cudaGetSymbolAddress((void**)&p_delta,g_delta);
    cudaGetSymbolAddress((void**)&p_gate, g_gate);

    float* pS = (out_size >= 4327424) ? out + 4194304 : p_qkv;
    float* pZ = (out_size >= 4327424) ? out + 4325376 : p_qkv + 4096;

    static cudaStream_t s1 = nullptr;
    static cudaEvent_t e1 = nullptr, e2 = nullptr;
    if (!s1) {
        cudaStreamCreateWithFlags(&s1, cudaStreamNonBlocking);
        cudaEventCreateWithFlags(&e1, cudaEventDisableTiming);
        cudaEventCreateWithFlags(&e2, cudaEventDisableTiming);
    }

    cudaFuncSetAttribute(gemm_tf32_t<false>, cudaFuncAttributeMaxDynamicSharedMemorySize, GEMM_SMEM_FAST);
    cudaFuncSetAttribute(gemm_tf32_t<true>,  cudaFuncAttributeMaxDynamicSharedMemorySize, GEMM_SMEM_P3);
    cudaFuncSetAttribute(attn_mma, cudaFuncAttributeMaxDynamicSharedMemorySize, ATTN_SMEM);

    // fork immediately: s1 = entire delta branch
    cudaEventRecord(e1, 0);
    cudaStreamWaitEvent(s1, e1, 0);
    gemm_tf32_t<true><<<dim3(8, 32), 256, GEMM_SMEM_P3, s1>>>(x, dWq, p_dqr, BL, Dm, Dm);
    gemm_tf32_t<true><<<dim3(8, 32), 256, GEMM_SMEM_P3, s1>>>(x, dWk, p_dkr, BL, Dm, Dm);
    gemm_tf32_t<true><<<dim3(8, 32), 256, GEMM_SMEM_P3, s1>>>(x, dWv, p_dv, BL, Dm, Dm);
    gemm_tf32_t<false><<<dim3(8, 32), 256, GEMM_SMEM_FAST, s1>>>(x, Wgate, p_gate, BL, Dm, Dm);
    gemm128<<<dim3(1, 32), 256, 0, s1>>>(x, Wbeta, p_beta, BL, Hh, Dm);
    conv_kernel<<<BL, 256, 0, s1>>>(p_dqr, p_dkr, cq_w, cq_b, ck_w, ck_b, p_dq, p_dk);
    scan_kernel<<<32, 256, 0, s1>>>(p_dq, p_dk, p_dv, p_beta, bbeta, p_ys, pS, pZ);
    gemm_tf32_t<false><<<dim3(8, 32), 256, GEMM_SMEM_FAST, s1>>>(p_ys, dWo, p_delta, BL, Dm, Dm);
    ln_kernel<<<BL, 256, 0, s1>>>(p_delta, ln_g, ln_b);
    ln_kernel<<<BL, 256, 0, s1>>>(p_delta, dn_g, dn_b);
    cudaEventRecord(e2, s1);

    // s0 = attention branch
    gemm_tf32_t<false><<<dim3(24, 32), 256, GEMM_SMEM_FAST>>>(x, Wqkv, p_qkv, BL, 3 * Dm, Dm);
    attn_mma<<<dim3(16, 32), 256, ATTN_SMEM>>>(p_qkv, p_attn);
    gemm_tf32_t<false><<<dim3(8, 32), 256, GEMM_SMEM_FAST>>>(p_attn, Wout, p_flash, BL, Dm, Dm);
    ln_kernel<<<BL, 256>>>(p_flash, fn_g, fn_b);

    // join + gate
    cudaStreamWaitEvent(0, e2, 0);
    gate_kernel<<<BL, 256>>>(p_gate, bgate, p_flash, p_delta, out);
}